// round 14
// baseline (speedup 1.0000x reference)
#include <cuda_runtime.h>
#include <math.h>
#include <stdint.h>

#define B 8
#define D 256
#define C 1024
#define HW 1024

typedef unsigned long long u64;

// ---------------- scratch (zero-initialized at module load; accumulators are
// re-zeroed by kernel tails each iteration so graph replays stay deterministic)
__device__ float g_A [B*C*HW];
__device__ float g_B2[B*C*HW];
__device__ float g_Z [B*D*HW];
__device__ float g_Sbo[B*C], g_SSbo[B*C];
__device__ float g_scale1[C], g_shift1[C];
__device__ float g_gap[B*C];
__device__ float g_kw[B*9];
__device__ float g_S2[B*C], g_SS2[B*C], g_Mx2[B*C], g_Mn2[B*C];
__device__ float g_Acoef[B*C], g_Bcoef[B*C];
__device__ float g_Cbd[B*D];
__device__ float g_sppsum[4*B*HW], g_sppmax[4*B*HW];
__device__ float g_spatt[B*HW];
__device__ float g_Sd3[D], g_SSd3[D];

__device__ __forceinline__ float gelu_f(float x){
    return 0.5f*x*(1.0f + erff(x*0.70710678118654752440f));
}
__device__ __forceinline__ unsigned tf32f(float v){
    unsigned r; asm("cvt.rna.tf32.f32 %0, %1;" : "=r"(r) : "f"(v)); return r;
}
__device__ __forceinline__ void mma8(float* c, const unsigned* a, const unsigned* b){
    asm volatile("mma.sync.aligned.m16n8k8.row.col.f32.tf32.tf32.f32 "
        "{%0,%1,%2,%3}, {%4,%5,%6,%7}, {%8,%9}, {%0,%1,%2,%3};"
        : "+f"(c[0]), "+f"(c[1]), "+f"(c[2]), "+f"(c[3])
        : "r"(a[0]), "r"(a[1]), "r"(a[2]), "r"(a[3]),
          "r"(b[0]), "r"(b[1]));
}
__device__ __forceinline__ uint32_t s32(const void* p){
    uint32_t a;
    asm("{ .reg .u64 t; cvta.to.shared.u64 t, %1; cvt.u32.u64 %0, t; }" : "=r"(a) : "l"(p));
    return a;
}
__device__ __forceinline__ void ldsm4(unsigned &r0, unsigned &r1, unsigned &r2, unsigned &r3, uint32_t a){
    asm volatile("ldmatrix.sync.aligned.m8n8.x4.shared.b16 {%0,%1,%2,%3}, [%4];"
        : "=r"(r0), "=r"(r1), "=r"(r2), "=r"(r3) : "r"(a));
}

// ================= GEMM1: tf32 mma.sync + ldmatrix, CTA 128x128, warps 4Mx2N =
__global__ __launch_bounds__(256,2) void k_gemm1(const float* __restrict__ x,
                                                 const float* __restrict__ w1,
                                                 const float* __restrict__ b1){
    const int b = blockIdx.z;
    const int oBase = blockIdx.y<<7, sBase = blockIdx.x<<7;
    const int tid = threadIdx.x, lane = tid&31, wid = tid>>5;
    const int g = lane>>2, t = lane&3;
    const int o0 = (wid&3)<<5, s0 = (wid>>2)<<6;
    __shared__ __align__(16) unsigned Ws[2][128][20];
    __shared__ __align__(16) unsigned Xs[2][128][20];

    float acc[2][8][4];
    #pragma unroll
    for (int mi=0;mi<2;mi++){
        #pragma unroll
        for (int ni=0;ni<8;ni++){
            #pragma unroll
            for (int r=0;r<4;r++) acc[mi][ni][r]=0.f;
        }
    }

    const int rl = tid>>1, kq = (tid&1)*8;
    const float* wp = w1 + (size_t)(oBase+rl)*D + kq;
    const float* xp = x + (size_t)(b*HW + sBase + rl)*D + kq;

    float4 wv0 = *reinterpret_cast<const float4*>(wp);
    float4 wv1 = *reinterpret_cast<const float4*>(wp+4);
    float4 xv0 = *reinterpret_cast<const float4*>(xp);
    float4 xv1 = *reinterpret_cast<const float4*>(xp+4);

    const int a_row = o0 + ((lane>>3)&1)*8 + (lane&7);
    const int a_col = (lane>>4)<<2;
    const int b_row = s0 + ((lane>>4)&1)*8 + (lane&7);
    const int b_col = ((lane>>3)&1)*4;
    const uint32_t aBase = s32(&Ws[0][a_row][a_col]);
    const uint32_t bBase = s32(&Xs[0][b_row][b_col]);
    const uint32_t BUFO = 128*20*4;
    const uint32_t T16  = 16*20*4;

    const int NC = D/16;  // 16
    for (int ck=0; ck<NC; ck++){
        const int bf = ck&1;
        {
            uint4 q0, q1;
            q0.x=tf32f(wv0.x); q0.y=tf32f(wv0.y); q0.z=tf32f(wv0.z); q0.w=tf32f(wv0.w);
            q1.x=tf32f(wv1.x); q1.y=tf32f(wv1.y); q1.z=tf32f(wv1.z); q1.w=tf32f(wv1.w);
            *reinterpret_cast<uint4*>(&Ws[bf][rl][kq])   = q0;
            *reinterpret_cast<uint4*>(&Ws[bf][rl][kq+4]) = q1;
            q0.x=tf32f(xv0.x); q0.y=tf32f(xv0.y); q0.z=tf32f(xv0.z); q0.w=tf32f(xv0.w);
            q1.x=tf32f(xv1.x); q1.y=tf32f(xv1.y); q1.z=tf32f(xv1.z); q1.w=tf32f(xv1.w);
            *reinterpret_cast<uint4*>(&Xs[bf][rl][kq])   = q0;
            *reinterpret_cast<uint4*>(&Xs[bf][rl][kq+4]) = q1;
        }
        __syncthreads();
        if (ck+1 < NC){
            int koff = (ck+1)*16;
            wv0 = *reinterpret_cast<const float4*>(wp + koff);
            wv1 = *reinterpret_cast<const float4*>(wp + koff + 4);
            xv0 = *reinterpret_cast<const float4*>(xp + koff);
            xv1 = *reinterpret_cast<const float4*>(xp + koff + 4);
        }
        const uint32_t bo = bf ? BUFO : 0u;
        #pragma unroll
        for (int ks=0; ks<2; ks++){
            const uint32_t ko = bo + ks*32;
            unsigned af[2][4];
            ldsm4(af[0][0],af[0][1],af[0][2],af[0][3], aBase + ko);
            ldsm4(af[1][0],af[1][1],af[1][2],af[1][3], aBase + ko + T16);
            unsigned bq[4][4];
            #pragma unroll
            for (int np=0;np<4;np++)
                ldsm4(bq[np][0],bq[np][1],bq[np][2],bq[np][3], bBase + ko + np*T16);
            #pragma unroll
            for (int mi=0;mi<2;mi++){
                #pragma unroll
                for (int ni=0;ni<8;ni++) mma8(acc[mi][ni], af[mi], &bq[ni>>1][(ni&1)*2]);
            }
        }
    }
    #pragma unroll
    for (int mi=0;mi<2;mi++){
        #pragma unroll
        for (int h=0;h<2;h++){
            int o = oBase + o0 + (mi<<4) + (h<<3) + g;
            float bias = b1[o];
            float s_=0.f, ss_=0.f;
            float* dst = &g_A[(((size_t)b*C + o)<<10) + sBase + s0];
            #pragma unroll
            for (int ni=0;ni<8;ni++){
                float v0 = gelu_f(acc[mi][ni][2*h  ] + bias);
                float v1 = gelu_f(acc[mi][ni][2*h+1] + bias);
                *reinterpret_cast<float2*>(dst + (ni<<3) + 2*t) = make_float2(v0,v1);
                s_ += v0+v1; ss_ += v0*v0 + v1*v1;
            }
            s_  += __shfl_xor_sync(0xffffffffu, s_, 1);
            s_  += __shfl_xor_sync(0xffffffffu, s_, 2);
            ss_ += __shfl_xor_sync(0xffffffffu, ss_, 1);
            ss_ += __shfl_xor_sync(0xffffffffu, ss_, 2);
            if (t==0){
                atomicAdd(&g_Sbo [b*C+o], s_);
                atomicAdd(&g_SSbo[b*C+o], ss_);
            }
        }
    }
}

// ---------------- BN1 finalize + GAP ----------------
__global__ void k_bn1fin(const float* __restrict__ g1, const float* __restrict__ be1){
    int o = blockIdx.x*256 + threadIdx.x;
    if (o >= C) return;
    float S=0.f, SS=0.f;
    for (int b=0;b<B;b++){ S += g_Sbo[b*C+o]; SS += g_SSbo[b*C+o]; }
    float m = S*(1.f/8192.f), v = SS*(1.f/8192.f) - m*m;
    float rs = rsqrtf(v + 1e-5f);
    float sc = rs*g1[o], sh = be1[o] - m*sc;
    g_scale1[o]=sc; g_shift1[o]=sh;
    for (int b=0;b<B;b++)
        g_gap[b*C+o] = g_Sbo[b*C+o]*(1.f/1024.f)*sc + sh;
}

// ---------------- dynw: FC1 (warp per 4 outputs) + FC2 + softmax, one kernel --
__global__ __launch_bounds__(1024) void k_dynw(const float* __restrict__ aw1,
                                               const float* __restrict__ ab1,
                                               const float* __restrict__ aw2,
                                               const float* __restrict__ ab2){
    int b = blockIdx.x, tid = threadIdx.x;
    int w = tid>>5, lane = tid&31;
    __shared__ float h1s[128];
    __shared__ float logits[9];
    const float4* gp = reinterpret_cast<const float4*>(&g_gap[b*C]);
    float4 gv[8];
    #pragma unroll
    for (int i=0;i<8;i++) gv[i] = gp[lane + 32*i];
    #pragma unroll
    for (int r=0;r<4;r++){
        int o = (w<<2) + r;
        const float4* row = reinterpret_cast<const float4*>(&aw1[(size_t)o*C]);
        float a = 0.f;
        #pragma unroll
        for (int i=0;i<8;i++){
            float4 wv = row[lane + 32*i];
            a += wv.x*gv[i].x + wv.y*gv[i].y + wv.z*gv[i].z + wv.w*gv[i].w;
        }
        #pragma unroll
        for (int off=16;off;off>>=1) a += __shfl_down_sync(0xffffffffu, a, off);
        if (lane==0) h1s[o] = fmaxf(a + ab1[o], 0.f);
    }
    __syncthreads();
    if (w < 9){
        float4 q = reinterpret_cast<const float4*>(&aw2[w*128])[lane];
        const float* hh = &h1s[lane*4];
        float l = q.x*hh[0] + q.y*hh[1] + q.z*hh[2] + q.w*hh[3];
        #pragma unroll
        for (int off=16;off;off>>=1) l += __shfl_down_sync(0xffffffffu, l, off);
        if (lane==0) logits[w] = l + ab2[w];
    }
    __syncthreads();
    if (tid==0){
        float mx = logits[0];
        for (int jj=1;jj<9;jj++) mx = fmaxf(mx, logits[jj]);
        float e[9], Zs=0.f;
        for (int jj=0;jj<9;jj++){ e[jj]=expf(logits[jj]-mx); Zs+=e[jj]; }
        float inv = 1.f/Zs;
        for (int jj=0;jj<9;jj++) g_kw[b*9+jj] = e[jj]*inv;
    }
}

// ---- dynamic depthwise conv + gelu + BN2 stats: 4 adjacent rows per thread --
__global__ __launch_bounds__(256) void k_dynconv(){
    const int o = blockIdx.x, b = blockIdx.y;
    const int tid = threadIdx.x;
    const int w = tid>>5, lane = tid&31;
    __shared__ float sm[34][35];
    __shared__ float kwsh[9];
    __shared__ float r4[4][8];
    if (tid < 9) kwsh[tid] = g_kw[b*9 + tid];
    if (b == 0 && tid < 16){
        int bb = tid & 7;
        if (tid < 8) g_Sbo [bb*C + o] = 0.f;
        else         g_SSbo[bb*C + o] = 0.f;
    }
    if (tid < 132){
        if (tid < 34)       sm[0][tid] = 0.f;
        else if (tid < 68)  sm[33][tid-34] = 0.f;
        else if (tid < 100) sm[tid-68+1][0] = 0.f;
        else                sm[tid-100+1][33] = 0.f;
    }
    const float sc = g_scale1[o], sh = g_shift1[o];
    const float* plane = &g_A[((size_t)(b*C + o))<<10];
    {
        int r = tid>>3, c4 = (tid&7)<<2;
        float4 v = *reinterpret_cast<const float4*>(&plane[(r<<5)+c4]);
        sm[r+1][c4+1] = v.x*sc+sh;
        sm[r+1][c4+2] = v.y*sc+sh;
        sm[r+1][c4+3] = v.z*sc+sh;
        sm[r+1][c4+4] = v.w*sc+sh;
    }
    __syncthreads();
    // warp w handles rows 4w..4w+3, lane = column; 6x3 register window
    const int c = lane, rb = w<<2;
    float v[6][3];
    #pragma unroll
    for (int k=0;k<6;k++){
        #pragma unroll
        for (int j=0;j<3;j++) v[k][j] = sm[rb+k][c+j];
    }
    float lsum=0.f, lss=0.f, lmx=-3.4e38f, lmn=3.4e38f;
    float* dst = &g_B2[(((size_t)(b*C + o))<<10)];
    #pragma unroll
    for (int rr=0;rr<4;rr++){
        float a = 0.f;
        #pragma unroll
        for (int i=0;i<3;i++){
            #pragma unroll
            for (int j=0;j<3;j++) a += kwsh[i*3+j]*v[rr+i][j];
        }
        float g = gelu_f(a);
        dst[((rb+rr)<<5) + c] = g;
        lsum += g; lss += g*g;
        lmx = fmaxf(lmx, g); lmn = fminf(lmn, g);
    }
    #pragma unroll
    for (int off=16;off;off>>=1){
        lsum += __shfl_down_sync(0xffffffffu, lsum, off);
        lss  += __shfl_down_sync(0xffffffffu, lss,  off);
        lmx = fmaxf(lmx, __shfl_down_sync(0xffffffffu, lmx, off));
        lmn = fminf(lmn, __shfl_down_sync(0xffffffffu, lmn, off));
    }
    if (lane==0){ r4[0][w]=lsum; r4[1][w]=lss; r4[2][w]=lmx; r4[3][w]=lmn; }
    __syncthreads();
    if (tid==0){
        float S=0,SS=0,MX=-3.4e38f,MN=3.4e38f;
        for (int i=0;i<8;i++){ S+=r4[0][i]; SS+=r4[1][i]; MX=fmaxf(MX,r4[2][i]); MN=fminf(MN,r4[3][i]); }
        g_S2[b*C+o]=S; g_SS2[b*C+o]=SS; g_Mx2[b*C+o]=MX; g_Mn2[b*C+o]=MN;
    }
}

// ---------------- BN2-finalize + channel attention + Cbd fused ----------------
__global__ __launch_bounds__(512) void k_cattcbd(const float* __restrict__ g2,
                                                 const float* __restrict__ be2,
                                                 const float* __restrict__ ca_w1,
                                                 const float* __restrict__ ca_w2,
                                                 const float* __restrict__ pw){
    int b = blockIdx.x, tid = threadIdx.x;
    int w = tid>>5, lane = tid&31;
    __shared__ float sav[C], smv[C], s2c[C], s2h[C], hsum[64], sBc[C];
    for (int i=tid;i<C;i+=512){
        float S=0.f, SS=0.f;
        #pragma unroll
        for (int bb=0;bb<B;bb++){ S += g_S2[bb*C+i]; SS += g_SS2[bb*C+i]; }
        float m = S*(1.f/8192.f), v = SS*(1.f/8192.f) - m*m;
        float rs = rsqrtf(v + 1e-5f);
        float sc = rs*g2[i], sh = be2[i] - m*sc;
        s2c[i]=sc; s2h[i]=sh;
        sav[i] = g_S2[b*C+i]*(1.f/1024.f)*sc + sh;
        float pre = (sc >= 0.f) ? g_Mx2[b*C+i] : g_Mn2[b*C+i];
        smv[i] = pre*sc + sh;
    }
    __syncthreads();
    #pragma unroll
    for (int r=0;r<4;r++){
        int o = (w<<2) + r;
        const float* row = &ca_w1[(size_t)o*C];
        float aa=0.f, am=0.f;
        #pragma unroll 8
        for (int c=lane;c<C;c+=32){ float rv=row[c]; aa += rv*sav[c]; am += rv*smv[c]; }
        #pragma unroll
        for (int off=16;off;off>>=1){
            aa += __shfl_down_sync(0xffffffffu, aa, off);
            am += __shfl_down_sync(0xffffffffu, am, off);
        }
        if (lane==0) hsum[o] = fmaxf(aa,0.f) + fmaxf(am,0.f);
    }
    __syncthreads();
    #pragma unroll
    for (int r=0;r<2;r++){
        int c = tid + (r<<9);
        const float4* w2r = reinterpret_cast<const float4*>(&ca_w2[(size_t)c*64]);
        float a = 0.f;
        #pragma unroll
        for (int j=0;j<16;j++){
            float4 q = w2r[j];
            const float* hh = &hsum[j*4];
            a += q.x*hh[0] + q.y*hh[1] + q.z*hh[2] + q.w*hh[3];
        }
        float s = 1.f/(1.f + expf(-a));
        float Av = s*s2c[c], Bv = s*s2h[c];
        g_Acoef[b*C+c] = Av; g_Bcoef[b*C+c] = Bv; sBc[c] = Bv;
    }
    __syncthreads();
    #pragma unroll
    for (int r=0;r<16;r++){
        int d = w + (r<<4);
        const float* row = &pw[(size_t)d*C];
        float a = 0.f;
        #pragma unroll 8
        for (int c=lane;c<C;c+=32) a += row[c]*sBc[c];
        #pragma unroll
        for (int off=16;off;off>>=1) a += __shfl_down_sync(0xffffffffu, a, off);
        if (lane==0) g_Cbd[b*D+d] = a;
    }
}

// ---------------- spatial mean/max partials ----------------
__global__ __launch_bounds__(1024) void k_spstats(){
    int b = blockIdx.z, csp = blockIdx.y, sblk = blockIdx.x;
    int tid = threadIdx.x;
    int sl = tid & 63, cg = tid >> 6;
    int s4 = sblk*64 + sl;
    const float4* base4 = reinterpret_cast<const float4*>(&g_B2[((size_t)b)<<20]);
    const float* Ac = &g_Acoef[b*C];
    const float* Bc = &g_Bcoef[b*C];
    float4 sum = make_float4(0,0,0,0);
    float4 mx  = make_float4(-3.4e38f,-3.4e38f,-3.4e38f,-3.4e38f);
    int c0 = csp*256 + cg*16;
    #pragma unroll 4
    for (int c=c0;c<c0+16;c++){
        float4 v = base4[(c<<8)+s4];
        float a = Ac[c], bb = Bc[c];
        v.x = a*v.x+bb; v.y = a*v.y+bb; v.z = a*v.z+bb; v.w = a*v.w+bb;
        sum.x += v.x; sum.y += v.y; sum.z += v.z; sum.w += v.w;
        mx.x = fmaxf(mx.x,v.x); mx.y = fmaxf(mx.y,v.y);
        mx.z = fmaxf(mx.z,v.z); mx.w = fmaxf(mx.w,v.w);
    }
    __shared__ float4 rs[16][64];
    __shared__ float4 rm[16][64];
    rs[cg][sl] = sum; rm[cg][sl] = mx;
    __syncthreads();
    if (tid < 64){
        float4 S = rs[0][tid], M = rm[0][tid];
        #pragma unroll
        for (int g=1; g<16; g++){
            float4 s2 = rs[g][tid], m2 = rm[g][tid];
            S.x+=s2.x; S.y+=s2.y; S.z+=s2.z; S.w+=s2.w;
            M.x=fmaxf(M.x,m2.x); M.y=fmaxf(M.y,m2.y); M.z=fmaxf(M.z,m2.z); M.w=fmaxf(M.w,m2.w);
        }
        int s4o = sblk*64 + tid;
        reinterpret_cast<float4*>(&g_sppsum[(csp*B + b)*HW])[s4o] = S;
        reinterpret_cast<float4*>(&g_sppmax[(csp*B + b)*HW])[s4o] = M;
    }
}

// ---------------- 7x7 spatial conv + sigmoid (+ zero Sd3 before gemm2) -------
__global__ void k_spconv(const float* __restrict__ sw, const float* __restrict__ sb){
    int b = blockIdx.x, tid = threadIdx.x;
    __shared__ float sa[1024], sx[1024];
    __shared__ float kw[98];
    if (b == 0){ g_Sd3[tid] = 0.f; g_SSd3[tid] = 0.f; }
    for (int i=tid;i<1024;i+=256){
        float s0 = g_sppsum[(0*B+b)*HW+i] + g_sppsum[(1*B+b)*HW+i]
                 + g_sppsum[(2*B+b)*HW+i] + g_sppsum[(3*B+b)*HW+i];
        float m0 = fmaxf(fmaxf(g_sppmax[(0*B+b)*HW+i], g_sppmax[(1*B+b)*HW+i]),
                         fmaxf(g_sppmax[(2*B+b)*HW+i], g_sppmax[(3*B+b)*HW+i]));
        sa[i] = s0*(1.f/1024.f);
        sx[i] = m0;
    }
    if (tid < 98) kw[tid] = sw[tid];
    __syncthreads();
    float bias = sb[0];
    for (int p=tid;p<1024;p+=256){
        int ph = p>>5, pw_ = p&31;
        float acc = bias;
        #pragma unroll
        for (int i=0;i<7;i++){
            int hh = ph + i - 3;
            if ((unsigned)hh >= 32u) continue;
            #pragma unroll
            for (int j=0;j<7;j++){
                int ww = pw_ + j - 3;
                if ((unsigned)ww >= 32u) continue;
                acc += kw[i*7+j]*sa[(hh<<5)+ww] + kw[49+i*7+j]*sx[(hh<<5)+ww];
            }
        }
        g_spatt[b*HW+p] = 1.f/(1.f + expf(-acc));
    }
}

// ================= GEMM2: tf32 mma.sync + ldmatrix A, CTA 64x128, warps 2Mx4N =
__global__ __launch_bounds__(256,3) void k_gemm2(const float* __restrict__ pw,
                                                 const float* __restrict__ pb){
    const int b = blockIdx.z;
    const int dBase = blockIdx.y<<6, sBase = blockIdx.x<<7;
    const int tid = threadIdx.x, lane = tid&31, wid = tid>>5;
    const int g = lane>>2, t = lane&3;
    const int d0 = (wid&1)<<5, s0 = (wid>>1)<<5;
    __shared__ __align__(16) unsigned Ws[2][64][20];
    __shared__ __align__(16) unsigned Xs[2][16][136];

    float acc[2][4][4];
    #pragma unroll
    for (int mi=0;mi<2;mi++){
        #pragma unroll
        for (int ni=0;ni<4;ni++){
            #pragma unroll
            for (int r=0;r<4;r++) acc[mi][ni][r]=0.f;
        }
    }

    const float* Ac  = &g_Acoef[b*C];
    const float* src = &g_B2[((size_t)b)<<20];
    const int rw = tid>>2, kqw = (tid&3)*4;   // W: 64 rows x 16 k
    const int kx = tid>>4, sqx = (tid&15)*8;  // X: 16 k rows x 128 s
    const float* wp = pw + (size_t)(dBase+rw)*C + kqw;
    const float* xp = src + ((size_t)kx<<10) + sBase + sqx;

    float4 wv  = *reinterpret_cast<const float4*>(wp);
    float4 xv0 = *reinterpret_cast<const float4*>(xp);
    float4 xv1 = *reinterpret_cast<const float4*>(xp+4);
    float  av  = Ac[kx];

    const int a_row = d0 + ((lane>>3)&1)*8 + (lane&7);
    const int a_col = (lane>>4)<<2;
    const uint32_t aBase = s32(&Ws[0][a_row][a_col]);
    const uint32_t BUFO = 64*20*4;
    const uint32_t T16  = 16*20*4;

    const int NC = C/16;  // 64
    for (int ck=0; ck<NC; ck++){
        const int bf = ck&1;
        {
            uint4 q;
            q.x=tf32f(wv.x); q.y=tf32f(wv.y); q.z=tf32f(wv.z); q.w=tf32f(wv.w);
            *reinterpret_cast<uint4*>(&Ws[bf][rw][kqw]) = q;
            uint4 p0, p1;
            p0.x=tf32f(xv0.x*av); p0.y=tf32f(xv0.y*av); p0.z=tf32f(xv0.z*av); p0.w=tf32f(xv0.w*av);
            p1.x=tf32f(xv1.x*av); p1.y=tf32f(xv1.y*av); p1.z=tf32f(xv1.z*av); p1.w=tf32f(xv1.w*av);
            *reinterpret_cast<uint4*>(&Xs[bf][kx][sqx])   = p0;
            *reinterpret_cast<uint4*>(&Xs[bf][kx][sqx+4]) = p1;
        }
        __syncthreads();
        if (ck+1 < NC){
            int koff = (ck+1)*16;
            wv  = *reinterpret_cast<const float4*>(wp + koff);
            xv0 = *reinterpret_cast<const float4*>(xp + ((size_t)koff<<10));
            xv1 = *reinterpret_cast<const float4*>(xp + ((size_t)koff<<10) + 4);
            av  = Ac[koff + kx];
        }
        const uint32_t bo = bf ? BUFO : 0u;
        #pragma unroll
        for (int ks=0; ks<2; ks++){
            const int kb = ks*8;
            unsigned af[2][4];
            ldsm4(af[0][0],af[0][1],af[0][2],af[0][3], aBase + bo + ks*32);
            ldsm4(af[1][0],af[1][1],af[1][2],af[1][3], aBase + bo + ks*32 + T16);
            unsigned bfr[4][2];
            #pragma unroll
            for (int ni=0;ni<4;ni++){
                bfr[ni][0] = Xs[bf][kb+t  ][s0+(ni<<3)+g];
                bfr[ni][1] = Xs[bf][kb+t+4][s0+(ni<<3)+g];
            }
            #pragma unroll
            for (int mi=0;mi<2;mi++){
                #pragma unroll
                for (int ni=0;ni<4;ni++) mma8(acc[mi][ni], af[mi], bfr[ni]);
            }
        }
    }
    // epilogue: spatial att + Cbd + pb, write Z, BN3 stats
    #pragma unroll
    for (int mi=0;mi<2;mi++){
        #pragma unroll
        for (int h=0;h<2;h++){
            int d = dBase + d0 + (mi<<4) + (h<<3) + g;
            float cb = g_Cbd[b*D+d], pbv = pb[d];
            float s_=0.f, ss_=0.f;
            float* dst = &g_Z[(((size_t)b*D + d)<<10) + sBase + s0];
            #pragma unroll
            for (int ni=0;ni<4;ni++){
                int sof = (ni<<3) + 2*t;
                float2 sp = *reinterpret_cast<const float2*>(&g_spatt[b*HW + sBase + s0 + sof]);
                float z0 = sp.x*(acc[mi][ni][2*h  ] + cb) + pbv;
                float z1 = sp.y*(acc[mi][ni][2*h+1] + cb) + pbv;
                *reinterpret_cast<float2*>(dst + sof) = make_float2(z0,z1);
                s_ += z0+z1; ss_ += z0*z0 + z1*z1;
            }
            s_  += __shfl_xor_sync(0xffffffffu, s_, 1);
            s_  += __shfl_xor_sync(0xffffffffu, s_, 2);
            ss_ += __shfl_xor_sync(0xffffffffu, ss_, 1);
            ss_ += __shfl_xor_sync(0xffffffffu, ss_, 2);
            if (t==0){
                atomicAdd(&g_Sd3 [d], s_);
                atomicAdd(&g_SSd3[d], ss_);
            }
        }
    }
}

// ---------------- transpose + BN3 (inline finalize) + residual ----------------
__global__ void k_out(const float* __restrict__ x, float* __restrict__ out,
                      const float* __restrict__ g3, const float* __restrict__ be3){
    const int b = blockIdx.z;
    const int dB = blockIdx.y<<5, sB = blockIdx.x<<5;
    const int tx = threadIdx.x, ty = threadIdx.y;
    __shared__ float sm[32][33];
    #pragma unroll
    for (int r=0;r<4;r++){
        int dd = ty + (r<<3);
        sm[dd][tx] = g_Z[(((size_t)b*D + dB + dd)<<10) + sB + tx];
    }
    int d = dB + tx;
    float m = g_Sd3[d]*(1.f/8192.f);
    float v = g_SSd3[d]*(1.f/8192.f) - m*m;
    float sc = rsqrtf(v + 1e-5f)*g3[d];
    float sh = be3[d] - m*sc;
    __syncthreads();
    #pragma unroll
    for (int r=0;r<4;r++){
        int ss = ty + (r<<3);
        size_t oi = ((size_t)(b*HW) + sB + ss)*D + d;
        out[oi] = x[oi] + sm[tx][ss]*sc + sh;
    }
}

extern "C" void kernel_launch(void* const* d_in, const int* in_sizes, int n_in,
                              void* d_out, int out_size){
    const float* x     = (const float*)d_in[0];
    const float* w1    = (const float*)d_in[1];
    const float* b1    = (const float*)d_in[2];
    const float* g1    = (const float*)d_in[3];
    const float* be1   = (const float*)d_in[4];
    const float* aw1   = (const float*)d_in[5];
    const float* ab1   = (const float*)d_in[6];
    const float* aw2   = (const float*)d_in[7];
    const float* ab2   = (const float*)d_in[8];
    const float* g2    = (const float*)d_in[9];
    const float* be2   = (const float*)d_in[10];
    const float* ca_w1 = (const float*)d_in[11];
    const float* ca_w2 = (const float*)d_in[12];
    const float* pw    = (const float*)d_in[13];
    const float* pb    = (const float*)d_in[14];
    const float* g3    = (const float*)d_in[15];
    const float* be3   = (const float*)d_in[16];
    const float* sw    = (const float*)d_in[17];
    const float* sb    = (const float*)d_in[18];
    float* out = (float*)d_out;

    k_gemm1   <<<dim3(8,8,B), 256>>>(x, w1, b1);
    k_bn1fin  <<<4, 256>>>(g1, be1);
    k_dynw    <<<B, 1024>>>(aw1, ab1, aw2, ab2);
    k_dynconv <<<dim3(C,B), 256>>>();
    k_cattcbd <<<B, 512>>>(g2, be2, ca_w1, ca_w2, pw);
    k_spstats <<<dim3(4,4,B), 1024>>>();
    k_spconv  <<<B, 256>>>(sw, sb);
    k_gemm2   <<<dim3(8,4,B), 256>>>(pw, pb);
    k_out     <<<dim3(32,8,B), dim3(32,8)>>>(x, out, g3, be3);
}

// round 15
// speedup vs baseline: 1.1622x; 1.1622x over previous
#include <cuda_runtime.h>
#include <math.h>
#include <stdint.h>

#define B 8
#define D 256
#define C 1024
#define HW 1024

typedef unsigned long long u64;

// ---------------- scratch (zero-initialized at module load; accumulators are
// re-zeroed by kernel tails each iteration so graph replays stay deterministic)
__device__ float g_A [B*C*HW];
__device__ float g_B2[B*C*HW];
__device__ float g_Z [B*D*HW];
__device__ float g_Sbo[B*C], g_SSbo[B*C];
__device__ float g_scale1[C], g_shift1[C];
__device__ float g_gap[B*C];
__device__ float g_kw[B*9];
__device__ float g_S2[B*C], g_SS2[B*C], g_Mx2[B*C], g_Mn2[B*C];
__device__ float g_Acoef[B*C], g_Bcoef[B*C];
__device__ float g_sppsum[4*B*HW], g_sppmax[4*B*HW];
__device__ float g_spatt[B*HW];
__device__ float g_Sd3[D], g_SSd3[D];

__device__ __forceinline__ float gelu_f(float x){
    return 0.5f*x*(1.0f + erff(x*0.70710678118654752440f));
}
__device__ __forceinline__ unsigned tf32f(float v){
    unsigned r; asm("cvt.rna.tf32.f32 %0, %1;" : "=r"(r) : "f"(v)); return r;
}
__device__ __forceinline__ void mma8(float* c, const unsigned* a, const unsigned* b){
    asm volatile("mma.sync.aligned.m16n8k8.row.col.f32.tf32.tf32.f32 "
        "{%0,%1,%2,%3}, {%4,%5,%6,%7}, {%8,%9}, {%0,%1,%2,%3};"
        : "+f"(c[0]), "+f"(c[1]), "+f"(c[2]), "+f"(c[3])
        : "r"(a[0]), "r"(a[1]), "r"(a[2]), "r"(a[3]),
          "r"(b[0]), "r"(b[1]));
}
__device__ __forceinline__ uint32_t s32(const void* p){
    uint32_t a;
    asm("{ .reg .u64 t; cvta.to.shared.u64 t, %1; cvt.u32.u64 %0, t; }" : "=r"(a) : "l"(p));
    return a;
}
__device__ __forceinline__ void ldsm4(unsigned &r0, unsigned &r1, unsigned &r2, unsigned &r3, uint32_t a){
    asm volatile("ldmatrix.sync.aligned.m8n8.x4.shared.b16 {%0,%1,%2,%3}, [%4];"
        : "=r"(r0), "=r"(r1), "=r"(r2), "=r"(r3) : "r"(a));
}

// ================= GEMM1: tf32 mma.sync + ldmatrix, CTA 128x128, warps 4Mx2N =
__global__ __launch_bounds__(256,2) void k_gemm1(const float* __restrict__ x,
                                                 const float* __restrict__ w1,
                                                 const float* __restrict__ b1){
    const int b = blockIdx.z;
    const int oBase = blockIdx.y<<7, sBase = blockIdx.x<<7;
    const int tid = threadIdx.x, lane = tid&31, wid = tid>>5;
    const int g = lane>>2, t = lane&3;
    const int o0 = (wid&3)<<5, s0 = (wid>>2)<<6;
    __shared__ __align__(16) unsigned Ws[2][128][20];
    __shared__ __align__(16) unsigned Xs[2][128][20];

    float acc[2][8][4];
    #pragma unroll
    for (int mi=0;mi<2;mi++){
        #pragma unroll
        for (int ni=0;ni<8;ni++){
            #pragma unroll
            for (int r=0;r<4;r++) acc[mi][ni][r]=0.f;
        }
    }

    const int rl = tid>>1, kq = (tid&1)*8;
    const float* wp = w1 + (size_t)(oBase+rl)*D + kq;
    const float* xp = x + (size_t)(b*HW + sBase + rl)*D + kq;

    float4 wv0 = *reinterpret_cast<const float4*>(wp);
    float4 wv1 = *reinterpret_cast<const float4*>(wp+4);
    float4 xv0 = *reinterpret_cast<const float4*>(xp);
    float4 xv1 = *reinterpret_cast<const float4*>(xp+4);

    const int a_row = o0 + ((lane>>3)&1)*8 + (lane&7);
    const int a_col = (lane>>4)<<2;
    const int b_row = s0 + ((lane>>4)&1)*8 + (lane&7);
    const int b_col = ((lane>>3)&1)*4;
    const uint32_t aBase = s32(&Ws[0][a_row][a_col]);
    const uint32_t bBase = s32(&Xs[0][b_row][b_col]);
    const uint32_t BUFO = 128*20*4;
    const uint32_t T16  = 16*20*4;

    const int NC = D/16;  // 16
    for (int ck=0; ck<NC; ck++){
        const int bf = ck&1;
        {
            uint4 q0, q1;
            q0.x=tf32f(wv0.x); q0.y=tf32f(wv0.y); q0.z=tf32f(wv0.z); q0.w=tf32f(wv0.w);
            q1.x=tf32f(wv1.x); q1.y=tf32f(wv1.y); q1.z=tf32f(wv1.z); q1.w=tf32f(wv1.w);
            *reinterpret_cast<uint4*>(&Ws[bf][rl][kq])   = q0;
            *reinterpret_cast<uint4*>(&Ws[bf][rl][kq+4]) = q1;
            q0.x=tf32f(xv0.x); q0.y=tf32f(xv0.y); q0.z=tf32f(xv0.z); q0.w=tf32f(xv0.w);
            q1.x=tf32f(xv1.x); q1.y=tf32f(xv1.y); q1.z=tf32f(xv1.z); q1.w=tf32f(xv1.w);
            *reinterpret_cast<uint4*>(&Xs[bf][rl][kq])   = q0;
            *reinterpret_cast<uint4*>(&Xs[bf][rl][kq+4]) = q1;
        }
        __syncthreads();
        if (ck+1 < NC){
            int koff = (ck+1)*16;
            wv0 = *reinterpret_cast<const float4*>(wp + koff);
            wv1 = *reinterpret_cast<const float4*>(wp + koff + 4);
            xv0 = *reinterpret_cast<const float4*>(xp + koff);
            xv1 = *reinterpret_cast<const float4*>(xp + koff + 4);
        }
        const uint32_t bo = bf ? BUFO : 0u;
        #pragma unroll
        for (int ks=0; ks<2; ks++){
            const uint32_t ko = bo + ks*32;
            unsigned af[2][4];
            ldsm4(af[0][0],af[0][1],af[0][2],af[0][3], aBase + ko);
            ldsm4(af[1][0],af[1][1],af[1][2],af[1][3], aBase + ko + T16);
            unsigned bq[4][4];
            #pragma unroll
            for (int np=0;np<4;np++)
                ldsm4(bq[np][0],bq[np][1],bq[np][2],bq[np][3], bBase + ko + np*T16);
            #pragma unroll
            for (int mi=0;mi<2;mi++){
                #pragma unroll
                for (int ni=0;ni<8;ni++) mma8(acc[mi][ni], af[mi], &bq[ni>>1][(ni&1)*2]);
            }
        }
    }
    #pragma unroll
    for (int mi=0;mi<2;mi++){
        #pragma unroll
        for (int h=0;h<2;h++){
            int o = oBase + o0 + (mi<<4) + (h<<3) + g;
            float bias = b1[o];
            float s_=0.f, ss_=0.f;
            float* dst = &g_A[(((size_t)b*C + o)<<10) + sBase + s0];
            #pragma unroll
            for (int ni=0;ni<8;ni++){
                float v0 = gelu_f(acc[mi][ni][2*h  ] + bias);
                float v1 = gelu_f(acc[mi][ni][2*h+1] + bias);
                *reinterpret_cast<float2*>(dst + (ni<<3) + 2*t) = make_float2(v0,v1);
                s_ += v0+v1; ss_ += v0*v0 + v1*v1;
            }
            s_  += __shfl_xor_sync(0xffffffffu, s_, 1);
            s_  += __shfl_xor_sync(0xffffffffu, s_, 2);
            ss_ += __shfl_xor_sync(0xffffffffu, ss_, 1);
            ss_ += __shfl_xor_sync(0xffffffffu, ss_, 2);
            if (t==0){
                atomicAdd(&g_Sbo [b*C+o], s_);
                atomicAdd(&g_SSbo[b*C+o], ss_);
            }
        }
    }
}

// ---------------- BN1 finalize + GAP ----------------
__global__ void k_bn1fin(const float* __restrict__ g1, const float* __restrict__ be1){
    int o = blockIdx.x*256 + threadIdx.x;
    if (o >= C) return;
    float S=0.f, SS=0.f;
    for (int b=0;b<B;b++){ S += g_Sbo[b*C+o]; SS += g_SSbo[b*C+o]; }
    float m = S*(1.f/8192.f), v = SS*(1.f/8192.f) - m*m;
    float rs = rsqrtf(v + 1e-5f);
    float sc = rs*g1[o], sh = be1[o] - m*sc;
    g_scale1[o]=sc; g_shift1[o]=sh;
    for (int b=0;b<B;b++)
        g_gap[b*C+o] = g_Sbo[b*C+o]*(1.f/1024.f)*sc + sh;
}

// ---------------- dynw: FC1 (warp per 4 outputs) + FC2 + softmax, one kernel --
__global__ __launch_bounds__(1024) void k_dynw(const float* __restrict__ aw1,
                                               const float* __restrict__ ab1,
                                               const float* __restrict__ aw2,
                                               const float* __restrict__ ab2){
    int b = blockIdx.x, tid = threadIdx.x;
    int w = tid>>5, lane = tid&31;
    __shared__ float h1s[128];
    __shared__ float logits[9];
    const float4* gp = reinterpret_cast<const float4*>(&g_gap[b*C]);
    float4 gv[8];
    #pragma unroll
    for (int i=0;i<8;i++) gv[i] = gp[lane + 32*i];
    #pragma unroll
    for (int r=0;r<4;r++){
        int o = (w<<2) + r;
        const float4* row = reinterpret_cast<const float4*>(&aw1[(size_t)o*C]);
        float a = 0.f;
        #pragma unroll
        for (int i=0;i<8;i++){
            float4 wv = row[lane + 32*i];
            a += wv.x*gv[i].x + wv.y*gv[i].y + wv.z*gv[i].z + wv.w*gv[i].w;
        }
        #pragma unroll
        for (int off=16;off;off>>=1) a += __shfl_down_sync(0xffffffffu, a, off);
        if (lane==0) h1s[o] = fmaxf(a + ab1[o], 0.f);
    }
    __syncthreads();
    if (w < 9){
        float4 q = reinterpret_cast<const float4*>(&aw2[w*128])[lane];
        const float* hh = &h1s[lane*4];
        float l = q.x*hh[0] + q.y*hh[1] + q.z*hh[2] + q.w*hh[3];
        #pragma unroll
        for (int off=16;off;off>>=1) l += __shfl_down_sync(0xffffffffu, l, off);
        if (lane==0) logits[w] = l + ab2[w];
    }
    __syncthreads();
    if (tid==0){
        float mx = logits[0];
        for (int jj=1;jj<9;jj++) mx = fmaxf(mx, logits[jj]);
        float e[9], Zs=0.f;
        for (int jj=0;jj<9;jj++){ e[jj]=expf(logits[jj]-mx); Zs+=e[jj]; }
        float inv = 1.f/Zs;
        for (int jj=0;jj<9;jj++) g_kw[b*9+jj] = e[jj]*inv;
    }
}

// ---- dynamic depthwise conv + gelu + BN2 stats: 4 adjacent rows per thread --
__global__ __launch_bounds__(256) void k_dynconv(){
    const int o = blockIdx.x, b = blockIdx.y;
    const int tid = threadIdx.x;
    const int w = tid>>5, lane = tid&31;
    __shared__ float sm[34][35];
    __shared__ float kwsh[9];
    __shared__ float r4[4][8];
    if (tid < 9) kwsh[tid] = g_kw[b*9 + tid];
    if (b == 0 && tid < 16){
        int bb = tid & 7;
        if (tid < 8) g_Sbo [bb*C + o] = 0.f;
        else         g_SSbo[bb*C + o] = 0.f;
    }
    if (tid < 132){
        if (tid < 34)       sm[0][tid] = 0.f;
        else if (tid < 68)  sm[33][tid-34] = 0.f;
        else if (tid < 100) sm[tid-68+1][0] = 0.f;
        else                sm[tid-100+1][33] = 0.f;
    }
    const float sc = g_scale1[o], sh = g_shift1[o];
    const float* plane = &g_A[((size_t)(b*C + o))<<10];
    {
        int r = tid>>3, c4 = (tid&7)<<2;
        float4 v = *reinterpret_cast<const float4*>(&plane[(r<<5)+c4]);
        sm[r+1][c4+1] = v.x*sc+sh;
        sm[r+1][c4+2] = v.y*sc+sh;
        sm[r+1][c4+3] = v.z*sc+sh;
        sm[r+1][c4+4] = v.w*sc+sh;
    }
    __syncthreads();
    // warp w handles rows 4w..4w+3, lane = column; 6x3 register window
    const int c = lane, rb = w<<2;
    float v[6][3];
    #pragma unroll
    for (int k=0;k<6;k++){
        #pragma unroll
        for (int j=0;j<3;j++) v[k][j] = sm[rb+k][c+j];
    }
    float lsum=0.f, lss=0.f, lmx=-3.4e38f, lmn=3.4e38f;
    float* dst = &g_B2[(((size_t)(b*C + o))<<10)];
    #pragma unroll
    for (int rr=0;rr<4;rr++){
        float a = 0.f;
        #pragma unroll
        for (int i=0;i<3;i++){
            #pragma unroll
            for (int j=0;j<3;j++) a += kwsh[i*3+j]*v[rr+i][j];
        }
        float g = gelu_f(a);
        dst[((rb+rr)<<5) + c] = g;
        lsum += g; lss += g*g;
        lmx = fmaxf(lmx, g); lmn = fminf(lmn, g);
    }
    #pragma unroll
    for (int off=16;off;off>>=1){
        lsum += __shfl_down_sync(0xffffffffu, lsum, off);
        lss  += __shfl_down_sync(0xffffffffu, lss,  off);
        lmx = fmaxf(lmx, __shfl_down_sync(0xffffffffu, lmx, off));
        lmn = fminf(lmn, __shfl_down_sync(0xffffffffu, lmn, off));
    }
    if (lane==0){ r4[0][w]=lsum; r4[1][w]=lss; r4[2][w]=lmx; r4[3][w]=lmn; }
    __syncthreads();
    if (tid==0){
        float S=0,SS=0,MX=-3.4e38f,MN=3.4e38f;
        for (int i=0;i<8;i++){ S+=r4[0][i]; SS+=r4[1][i]; MX=fmaxf(MX,r4[2][i]); MN=fminf(MN,r4[3][i]); }
        g_S2[b*C+o]=S; g_SS2[b*C+o]=SS; g_Mx2[b*C+o]=MX; g_Mn2[b*C+o]=MN;
    }
}

// ---------------- BN2-finalize + channel attention (Cbd folded into gemm2) ---
__global__ __launch_bounds__(512) void k_cattcbd(const float* __restrict__ g2,
                                                 const float* __restrict__ be2,
                                                 const float* __restrict__ ca_w1,
                                                 const float* __restrict__ ca_w2){
    int b = blockIdx.x, tid = threadIdx.x;
    int w = tid>>5, lane = tid&31;
    __shared__ float sav[C], smv[C], s2c[C], s2h[C], hsum[64];
    for (int i=tid;i<C;i+=512){
        float S=0.f, SS=0.f;
        #pragma unroll
        for (int bb=0;bb<B;bb++){ S += g_S2[bb*C+i]; SS += g_SS2[bb*C+i]; }
        float m = S*(1.f/8192.f), v = SS*(1.f/8192.f) - m*m;
        float rs = rsqrtf(v + 1e-5f);
        float sc = rs*g2[i], sh = be2[i] - m*sc;
        s2c[i]=sc; s2h[i]=sh;
        sav[i] = g_S2[b*C+i]*(1.f/1024.f)*sc + sh;
        float pre = (sc >= 0.f) ? g_Mx2[b*C+i] : g_Mn2[b*C+i];
        smv[i] = pre*sc + sh;
    }
    __syncthreads();
    #pragma unroll
    for (int r=0;r<4;r++){
        int o = (w<<2) + r;
        const float* row = &ca_w1[(size_t)o*C];
        float aa=0.f, am=0.f;
        #pragma unroll 8
        for (int c=lane;c<C;c+=32){ float rv=row[c]; aa += rv*sav[c]; am += rv*smv[c]; }
        #pragma unroll
        for (int off=16;off;off>>=1){
            aa += __shfl_down_sync(0xffffffffu, aa, off);
            am += __shfl_down_sync(0xffffffffu, am, off);
        }
        if (lane==0) hsum[o] = fmaxf(aa,0.f) + fmaxf(am,0.f);
    }
    __syncthreads();
    #pragma unroll
    for (int r=0;r<2;r++){
        int c = tid + (r<<9);
        const float4* w2r = reinterpret_cast<const float4*>(&ca_w2[(size_t)c*64]);
        float a = 0.f;
        #pragma unroll
        for (int j=0;j<16;j++){
            float4 q = w2r[j];
            const float* hh = &hsum[j*4];
            a += q.x*hh[0] + q.y*hh[1] + q.z*hh[2] + q.w*hh[3];
        }
        float s = 1.f/(1.f + expf(-a));
        g_Acoef[b*C+c] = s*s2c[c];
        g_Bcoef[b*C+c] = s*s2h[c];
    }
}

// ---------------- spatial mean/max partials ----------------
__global__ __launch_bounds__(1024) void k_spstats(){
    int b = blockIdx.z, csp = blockIdx.y, sblk = blockIdx.x;
    int tid = threadIdx.x;
    int sl = tid & 63, cg = tid >> 6;
    int s4 = sblk*64 + sl;
    const float4* base4 = reinterpret_cast<const float4*>(&g_B2[((size_t)b)<<20]);
    const float* Ac = &g_Acoef[b*C];
    const float* Bc = &g_Bcoef[b*C];
    float4 sum = make_float4(0,0,0,0);
    float4 mx  = make_float4(-3.4e38f,-3.4e38f,-3.4e38f,-3.4e38f);
    int c0 = csp*256 + cg*16;
    #pragma unroll 4
    for (int c=c0;c<c0+16;c++){
        float4 v = base4[(c<<8)+s4];
        float a = Ac[c], bb = Bc[c];
        v.x = a*v.x+bb; v.y = a*v.y+bb; v.z = a*v.z+bb; v.w = a*v.w+bb;
        sum.x += v.x; sum.y += v.y; sum.z += v.z; sum.w += v.w;
        mx.x = fmaxf(mx.x,v.x); mx.y = fmaxf(mx.y,v.y);
        mx.z = fmaxf(mx.z,v.z); mx.w = fmaxf(mx.w,v.w);
    }
    __shared__ float4 rs[16][64];
    __shared__ float4 rm[16][64];
    rs[cg][sl] = sum; rm[cg][sl] = mx;
    __syncthreads();
    if (tid < 64){
        float4 S = rs[0][tid], M = rm[0][tid];
        #pragma unroll
        for (int g=1; g<16; g++){
            float4 s2 = rs[g][tid], m2 = rm[g][tid];
            S.x+=s2.x; S.y+=s2.y; S.z+=s2.z; S.w+=s2.w;
            M.x=fmaxf(M.x,m2.x); M.y=fmaxf(M.y,m2.y); M.z=fmaxf(M.z,m2.z); M.w=fmaxf(M.w,m2.w);
        }
        int s4o = sblk*64 + tid;
        reinterpret_cast<float4*>(&g_sppsum[(csp*B + b)*HW])[s4o] = S;
        reinterpret_cast<float4*>(&g_sppmax[(csp*B + b)*HW])[s4o] = M;
    }
}

// ---------------- 7x7 spatial conv + sigmoid (+ zero Sd3 before gemm2) -------
__global__ void k_spconv(const float* __restrict__ sw, const float* __restrict__ sb){
    int b = blockIdx.x, tid = threadIdx.x;
    __shared__ float sa[1024], sx[1024];
    __shared__ float kw[98];
    if (b == 0){ g_Sd3[tid] = 0.f; g_SSd3[tid] = 0.f; }
    for (int i=tid;i<1024;i+=256){
        float s0 = g_sppsum[(0*B+b)*HW+i] + g_sppsum[(1*B+b)*HW+i]
                 + g_sppsum[(2*B+b)*HW+i] + g_sppsum[(3*B+b)*HW+i];
        float m0 = fmaxf(fmaxf(g_sppmax[(0*B+b)*HW+i], g_sppmax[(1*B+b)*HW+i]),
                         fmaxf(g_sppmax[(2*B+b)*HW+i], g_sppmax[(3*B+b)*HW+i]));
        sa[i] = s0*(1.f/1024.f);
        sx[i] = m0;
    }
    if (tid < 98) kw[tid] = sw[tid];
    __syncthreads();
    float bias = sb[0];
    for (int p=tid;p<1024;p+=256){
        int ph = p>>5, pw_ = p&31;
        float acc = bias;
        #pragma unroll
        for (int i=0;i<7;i++){
            int hh = ph + i - 3;
            if ((unsigned)hh >= 32u) continue;
            #pragma unroll
            for (int j=0;j<7;j++){
                int ww = pw_ + j - 3;
                if ((unsigned)ww >= 32u) continue;
                acc += kw[i*7+j]*sa[(hh<<5)+ww] + kw[49+i*7+j]*sx[(hh<<5)+ww];
            }
        }
        g_spatt[b*HW+p] = 1.f/(1.f + expf(-acc));
    }
}

// ======= GEMM2: tf32 mma.sync + ldmatrix A, CTA 64x128; X = Acoef*B2 + Bcoef =
__global__ __launch_bounds__(256,3) void k_gemm2(const float* __restrict__ pw,
                                                 const float* __restrict__ pb){
    const int b = blockIdx.z;
    const int dBase = blockIdx.y<<6, sBase = blockIdx.x<<7;
    const int tid = threadIdx.x, lane = tid&31, wid = tid>>5;
    const int g = lane>>2, t = lane&3;
    const int d0 = (wid&1)<<5, s0 = (wid>>1)<<5;
    __shared__ __align__(16) unsigned Ws[2][64][20];
    __shared__ __align__(16) unsigned Xs[2][16][136];

    float acc[2][4][4];
    #pragma unroll
    for (int mi=0;mi<2;mi++){
        #pragma unroll
        for (int ni=0;ni<4;ni++){
            #pragma unroll
            for (int r=0;r<4;r++) acc[mi][ni][r]=0.f;
        }
    }

    const float* Ac  = &g_Acoef[b*C];
    const float* Bc  = &g_Bcoef[b*C];
    const float* src = &g_B2[((size_t)b)<<20];
    const int rw = tid>>2, kqw = (tid&3)*4;   // W: 64 rows x 16 k
    const int kx = tid>>4, sqx = (tid&15)*8;  // X: 16 k rows x 128 s
    const float* wp = pw + (size_t)(dBase+rw)*C + kqw;
    const float* xp = src + ((size_t)kx<<10) + sBase + sqx;

    float4 wv  = *reinterpret_cast<const float4*>(wp);
    float4 xv0 = *reinterpret_cast<const float4*>(xp);
    float4 xv1 = *reinterpret_cast<const float4*>(xp+4);
    float  av  = Ac[kx];
    float  bv  = Bc[kx];

    const int a_row = d0 + ((lane>>3)&1)*8 + (lane&7);
    const int a_col = (lane>>4)<<2;
    const uint32_t aBase = s32(&Ws[0][a_row][a_col]);
    const uint32_t BUFO = 64*20*4;
    const uint32_t T16  = 16*20*4;

    const int NC = C/16;  // 64
    for (int ck=0; ck<NC; ck++){
        const int bf = ck&1;
        {
            uint4 q;
            q.x=tf32f(wv.x); q.y=tf32f(wv.y); q.z=tf32f(wv.z); q.w=tf32f(wv.w);
            *reinterpret_cast<uint4*>(&Ws[bf][rw][kqw]) = q;
            uint4 p0, p1;
            p0.x=tf32f(xv0.x*av+bv); p0.y=tf32f(xv0.y*av+bv);
            p0.z=tf32f(xv0.z*av+bv); p0.w=tf32f(xv0.w*av+bv);
            p1.x=tf32f(xv1.x*av+bv); p1.y=tf32f(xv1.y*av+bv);
            p1.z=tf32f(xv1.z*av+bv); p1.w=tf32f(xv1.w*av+bv);
            *reinterpret_cast<uint4*>(&Xs[bf][kx][sqx])   = p0;
            *reinterpret_cast<uint4*>(&Xs[bf][kx][sqx+4]) = p1;
        }
        __syncthreads();
        if (ck+1 < NC){
            int koff = (ck+1)*16;
            wv  = *reinterpret_cast<const float4*>(wp + koff);
            xv0 = *reinterpret_cast<const float4*>(xp + ((size_t)koff<<10));
            xv1 = *reinterpret_cast<const float4*>(xp + ((size_t)koff<<10) + 4);
            av  = Ac[koff + kx];
            bv  = Bc[koff + kx];
        }
        const uint32_t bo = bf ? BUFO : 0u;
        #pragma unroll
        for (int ks=0; ks<2; ks++){
            const int kb = ks*8;
            unsigned af[2][4];
            ldsm4(af[0][0],af[0][1],af[0][2],af[0][3], aBase + bo + ks*32);
            ldsm4(af[1][0],af[1][1],af[1][2],af[1][3], aBase + bo + ks*32 + T16);
            unsigned bfr[4][2];
            #pragma unroll
            for (int ni=0;ni<4;ni++){
                bfr[ni][0] = Xs[bf][kb+t  ][s0+(ni<<3)+g];
                bfr[ni][1] = Xs[bf][kb+t+4][s0+(ni<<3)+g];
            }
            #pragma unroll
            for (int mi=0;mi<2;mi++){
                #pragma unroll
                for (int ni=0;ni<4;ni++) mma8(acc[mi][ni], af[mi], bfr[ni]);
            }
        }
    }
    // epilogue: spatial att + pb, write Z, BN3 stats (Cbd already inside acc)
    #pragma unroll
    for (int mi=0;mi<2;mi++){
        #pragma unroll
        for (int h=0;h<2;h++){
            int d = dBase + d0 + (mi<<4) + (h<<3) + g;
            float pbv = pb[d];
            float s_=0.f, ss_=0.f;
            float* dst = &g_Z[(((size_t)b*D + d)<<10) + sBase + s0];
            #pragma unroll
            for (int ni=0;ni<4;ni++){
                int sof = (ni<<3) + 2*t;
                float2 sp = *reinterpret_cast<const float2*>(&g_spatt[b*HW + sBase + s0 + sof]);
                float z0 = sp.x*acc[mi][ni][2*h  ] + pbv;
                float z1 = sp.y*acc[mi][ni][2*h+1] + pbv;
                *reinterpret_cast<float2*>(dst + sof) = make_float2(z0,z1);
                s_ += z0+z1; ss_ += z0*z0 + z1*z1;
            }
            s_  += __shfl_xor_sync(0xffffffffu, s_, 1);
            s_  += __shfl_xor_sync(0xffffffffu, s_, 2);
            ss_ += __shfl_xor_sync(0xffffffffu, ss_, 1);
            ss_ += __shfl_xor_sync(0xffffffffu, ss_, 2);
            if (t==0){
                atomicAdd(&g_Sd3 [d], s_);
                atomicAdd(&g_SSd3[d], ss_);
            }
        }
    }
}

// ---------------- transpose + BN3 (inline finalize) + residual ----------------
__global__ void k_out(const float* __restrict__ x, float* __restrict__ out,
                      const float* __restrict__ g3, const float* __restrict__ be3){
    const int b = blockIdx.z;
    const int dB = blockIdx.y<<5, sB = blockIdx.x<<5;
    const int tx = threadIdx.x, ty = threadIdx.y;
    __shared__ float sm[32][33];
    #pragma unroll
    for (int r=0;r<4;r++){
        int dd = ty + (r<<3);
        sm[dd][tx] = g_Z[(((size_t)b*D + dB + dd)<<10) + sB + tx];
    }
    int d = dB + tx;
    float m = g_Sd3[d]*(1.f/8192.f);
    float v = g_SSd3[d]*(1.f/8192.f) - m*m;
    float sc = rsqrtf(v + 1e-5f)*g3[d];
    float sh = be3[d] - m*sc;
    __syncthreads();
    #pragma unroll
    for (int r=0;r<4;r++){
        int ss = ty + (r<<3);
        size_t oi = ((size_t)(b*HW) + sB + ss)*D + d;
        out[oi] = x[oi] + sm[tx][ss]*sc + sh;
    }
}

extern "C" void kernel_launch(void* const* d_in, const int* in_sizes, int n_in,
                              void* d_out, int out_size){
    const float* x     = (const float*)d_in[0];
    const float* w1    = (const float*)d_in[1];
    const float* b1    = (const float*)d_in[2];
    const float* g1    = (const float*)d_in[3];
    const float* be1   = (const float*)d_in[4];
    const float* aw1   = (const float*)d_in[5];
    const float* ab1   = (const float*)d_in[6];
    const float* aw2   = (const float*)d_in[7];
    const float* ab2   = (const float*)d_in[8];
    const float* g2    = (const float*)d_in[9];
    const float* be2   = (const float*)d_in[10];
    const float* ca_w1 = (const float*)d_in[11];
    const float* ca_w2 = (const float*)d_in[12];
    const float* pw    = (const float*)d_in[13];
    const float* pb    = (const float*)d_in[14];
    const float* g3    = (const float*)d_in[15];
    const float* be3   = (const float*)d_in[16];
    const float* sw    = (const float*)d_in[17];
    const float* sb    = (const float*)d_in[18];
    float* out = (float*)d_out;

    k_gemm1   <<<dim3(8,8,B), 256>>>(x, w1, b1);
    k_bn1fin  <<<4, 256>>>(g1, be1);
    k_dynw    <<<B, 1024>>>(aw1, ab1, aw2, ab2);
    k_dynconv <<<dim3(C,B), 256>>>();
    k_cattcbd <<<B, 512>>>(g2, be2, ca_w1, ca_w2);
    k_spstats <<<dim3(4,4,B), 1024>>>();
    k_spconv  <<<B, 256>>>(sw, sb);
    k_gemm2   <<<dim3(8,4,B), 256>>>(pw, pb);
    k_out     <<<dim3(32,8,B), dim3(32,8)>>>(x, out, g3, be3);
}

// round 16
// speedup vs baseline: 1.2019x; 1.0342x over previous
#include <cuda_runtime.h>
#include <math.h>
#include <stdint.h>

#define B 8
#define D 256
#define C 1024
#define HW 1024

typedef unsigned long long u64;

// ---------------- scratch (zero-initialized at module load; accumulators are
// re-zeroed by kernel tails each iteration so graph replays stay deterministic)
__device__ float g_A [B*C*HW];
__device__ float g_B2[B*C*HW];
__device__ float g_Z [B*D*HW];
__device__ float g_Sbo[B*C], g_SSbo[B*C];
__device__ float g_scale1[C], g_shift1[C];
__device__ float g_kw[B*9];
__device__ float g_S2[B*C], g_SS2[B*C], g_Mx2[B*C], g_Mn2[B*C];
__device__ float g_Acoef[B*C], g_Bcoef[B*C];
__device__ float g_sppsum[4*B*HW], g_sppmax[4*B*HW];
__device__ float g_spatt[B*HW];
__device__ float g_Sd3[D], g_SSd3[D];

__device__ __forceinline__ float gelu_f(float x){
    return 0.5f*x*(1.0f + erff(x*0.70710678118654752440f));
}
__device__ __forceinline__ unsigned tf32f(float v){
    unsigned r; asm("cvt.rna.tf32.f32 %0, %1;" : "=r"(r) : "f"(v)); return r;
}
__device__ __forceinline__ void mma8(float* c, const unsigned* a, const unsigned* b){
    asm volatile("mma.sync.aligned.m16n8k8.row.col.f32.tf32.tf32.f32 "
        "{%0,%1,%2,%3}, {%4,%5,%6,%7}, {%8,%9}, {%0,%1,%2,%3};"
        : "+f"(c[0]), "+f"(c[1]), "+f"(c[2]), "+f"(c[3])
        : "r"(a[0]), "r"(a[1]), "r"(a[2]), "r"(a[3]),
          "r"(b[0]), "r"(b[1]));
}
__device__ __forceinline__ uint32_t s32(const void* p){
    uint32_t a;
    asm("{ .reg .u64 t; cvta.to.shared.u64 t, %1; cvt.u32.u64 %0, t; }" : "=r"(a) : "l"(p));
    return a;
}
__device__ __forceinline__ void ldsm4(unsigned &r0, unsigned &r1, unsigned &r2, unsigned &r3, uint32_t a){
    asm volatile("ldmatrix.sync.aligned.m8n8.x4.shared.b16 {%0,%1,%2,%3}, [%4];"
        : "=r"(r0), "=r"(r1), "=r"(r2), "=r"(r3) : "r"(a));
}

// ================= GEMM1: tf32 mma.sync + ldmatrix, CTA 128x128, warps 4Mx2N =
__global__ __launch_bounds__(256,2) void k_gemm1(const float* __restrict__ x,
                                                 const float* __restrict__ w1,
                                                 const float* __restrict__ b1){
    const int b = blockIdx.z;
    const int oBase = blockIdx.y<<7, sBase = blockIdx.x<<7;
    const int tid = threadIdx.x, lane = tid&31, wid = tid>>5;
    const int g = lane>>2, t = lane&3;
    const int o0 = (wid&3)<<5, s0 = (wid>>2)<<6;
    __shared__ __align__(16) unsigned Ws[2][128][20];
    __shared__ __align__(16) unsigned Xs[2][128][20];

    float acc[2][8][4];
    #pragma unroll
    for (int mi=0;mi<2;mi++){
        #pragma unroll
        for (int ni=0;ni<8;ni++){
            #pragma unroll
            for (int r=0;r<4;r++) acc[mi][ni][r]=0.f;
        }
    }

    const int rl = tid>>1, kq = (tid&1)*8;
    const float* wp = w1 + (size_t)(oBase+rl)*D + kq;
    const float* xp = x + (size_t)(b*HW + sBase + rl)*D + kq;

    float4 wv0 = *reinterpret_cast<const float4*>(wp);
    float4 wv1 = *reinterpret_cast<const float4*>(wp+4);
    float4 xv0 = *reinterpret_cast<const float4*>(xp);
    float4 xv1 = *reinterpret_cast<const float4*>(xp+4);

    const int a_row = o0 + ((lane>>3)&1)*8 + (lane&7);
    const int a_col = (lane>>4)<<2;
    const int b_row = s0 + ((lane>>4)&1)*8 + (lane&7);
    const int b_col = ((lane>>3)&1)*4;
    const uint32_t aBase = s32(&Ws[0][a_row][a_col]);
    const uint32_t bBase = s32(&Xs[0][b_row][b_col]);
    const uint32_t BUFO = 128*20*4;
    const uint32_t T16  = 16*20*4;

    const int NC = D/16;  // 16
    for (int ck=0; ck<NC; ck++){
        const int bf = ck&1;
        {
            uint4 q0, q1;
            q0.x=tf32f(wv0.x); q0.y=tf32f(wv0.y); q0.z=tf32f(wv0.z); q0.w=tf32f(wv0.w);
            q1.x=tf32f(wv1.x); q1.y=tf32f(wv1.y); q1.z=tf32f(wv1.z); q1.w=tf32f(wv1.w);
            *reinterpret_cast<uint4*>(&Ws[bf][rl][kq])   = q0;
            *reinterpret_cast<uint4*>(&Ws[bf][rl][kq+4]) = q1;
            q0.x=tf32f(xv0.x); q0.y=tf32f(xv0.y); q0.z=tf32f(xv0.z); q0.w=tf32f(xv0.w);
            q1.x=tf32f(xv1.x); q1.y=tf32f(xv1.y); q1.z=tf32f(xv1.z); q1.w=tf32f(xv1.w);
            *reinterpret_cast<uint4*>(&Xs[bf][rl][kq])   = q0;
            *reinterpret_cast<uint4*>(&Xs[bf][rl][kq+4]) = q1;
        }
        __syncthreads();
        if (ck+1 < NC){
            int koff = (ck+1)*16;
            wv0 = *reinterpret_cast<const float4*>(wp + koff);
            wv1 = *reinterpret_cast<const float4*>(wp + koff + 4);
            xv0 = *reinterpret_cast<const float4*>(xp + koff);
            xv1 = *reinterpret_cast<const float4*>(xp + koff + 4);
        }
        const uint32_t bo = bf ? BUFO : 0u;
        #pragma unroll
        for (int ks=0; ks<2; ks++){
            const uint32_t ko = bo + ks*32;
            unsigned af[2][4];
            ldsm4(af[0][0],af[0][1],af[0][2],af[0][3], aBase + ko);
            ldsm4(af[1][0],af[1][1],af[1][2],af[1][3], aBase + ko + T16);
            unsigned bq[4][4];
            #pragma unroll
            for (int np=0;np<4;np++)
                ldsm4(bq[np][0],bq[np][1],bq[np][2],bq[np][3], bBase + ko + np*T16);
            #pragma unroll
            for (int mi=0;mi<2;mi++){
                #pragma unroll
                for (int ni=0;ni<8;ni++) mma8(acc[mi][ni], af[mi], &bq[ni>>1][(ni&1)*2]);
            }
        }
    }
    #pragma unroll
    for (int mi=0;mi<2;mi++){
        #pragma unroll
        for (int h=0;h<2;h++){
            int o = oBase + o0 + (mi<<4) + (h<<3) + g;
            float bias = b1[o];
            float s_=0.f, ss_=0.f;
            float* dst = &g_A[(((size_t)b*C + o)<<10) + sBase + s0];
            #pragma unroll
            for (int ni=0;ni<8;ni++){
                float v0 = gelu_f(acc[mi][ni][2*h  ] + bias);
                float v1 = gelu_f(acc[mi][ni][2*h+1] + bias);
                *reinterpret_cast<float2*>(dst + (ni<<3) + 2*t) = make_float2(v0,v1);
                s_ += v0+v1; ss_ += v0*v0 + v1*v1;
            }
            s_  += __shfl_xor_sync(0xffffffffu, s_, 1);
            s_  += __shfl_xor_sync(0xffffffffu, s_, 2);
            ss_ += __shfl_xor_sync(0xffffffffu, ss_, 1);
            ss_ += __shfl_xor_sync(0xffffffffu, ss_, 2);
            if (t==0){
                atomicAdd(&g_Sbo [b*C+o], s_);
                atomicAdd(&g_SSbo[b*C+o], ss_);
            }
        }
    }
}

// ------- dynw: BN1 finalize + GAP (in-smem) + FC1 + FC2 + softmax, one kernel
__global__ __launch_bounds__(1024) void k_dynw(const float* __restrict__ g1,
                                               const float* __restrict__ be1,
                                               const float* __restrict__ aw1,
                                               const float* __restrict__ ab1,
                                               const float* __restrict__ aw2,
                                               const float* __restrict__ ab2){
    int b = blockIdx.x, tid = threadIdx.x;
    int w = tid>>5, lane = tid&31;
    __shared__ float gaps[C];
    __shared__ float h1s[128];
    __shared__ float logits[9];
    // thread tid handles channel o = tid: BN1 finalize + gap
    {
        int o = tid;
        float S=0.f, SS=0.f;
        #pragma unroll
        for (int bb=0;bb<B;bb++){ S += g_Sbo[bb*C+o]; SS += g_SSbo[bb*C+o]; }
        float m = S*(1.f/8192.f), v = SS*(1.f/8192.f) - m*m;
        float rs = rsqrtf(v + 1e-5f);
        float sc = rs*g1[o], sh = be1[o] - m*sc;
        g_scale1[o]=sc; g_shift1[o]=sh;  // redundant identical writes across blocks: benign
        gaps[o] = g_Sbo[b*C+o]*(1.f/1024.f)*sc + sh;
    }
    __syncthreads();
    float4 gv[8];
    const float4* gp = reinterpret_cast<const float4*>(gaps);
    #pragma unroll
    for (int i=0;i<8;i++) gv[i] = gp[lane + 32*i];
    #pragma unroll
    for (int r=0;r<4;r++){
        int o = (w<<2) + r;
        const float4* row = reinterpret_cast<const float4*>(&aw1[(size_t)o*C]);
        float a = 0.f;
        #pragma unroll
        for (int i=0;i<8;i++){
            float4 wv = row[lane + 32*i];
            a += wv.x*gv[i].x + wv.y*gv[i].y + wv.z*gv[i].z + wv.w*gv[i].w;
        }
        #pragma unroll
        for (int off=16;off;off>>=1) a += __shfl_down_sync(0xffffffffu, a, off);
        if (lane==0) h1s[o] = fmaxf(a + ab1[o], 0.f);
    }
    __syncthreads();
    if (w < 9){
        float4 q = reinterpret_cast<const float4*>(&aw2[w*128])[lane];
        const float* hh = &h1s[lane*4];
        float l = q.x*hh[0] + q.y*hh[1] + q.z*hh[2] + q.w*hh[3];
        #pragma unroll
        for (int off=16;off;off>>=1) l += __shfl_down_sync(0xffffffffu, l, off);
        if (lane==0) logits[w] = l + ab2[w];
    }
    __syncthreads();
    if (tid==0){
        float mx = logits[0];
        for (int jj=1;jj<9;jj++) mx = fmaxf(mx, logits[jj]);
        float e[9], Zs=0.f;
        for (int jj=0;jj<9;jj++){ e[jj]=expf(logits[jj]-mx); Zs+=e[jj]; }
        float inv = 1.f/Zs;
        for (int jj=0;jj<9;jj++) g_kw[b*9+jj] = e[jj]*inv;
    }
}

// ---- dynamic depthwise conv + gelu + BN2 stats: 4 adjacent rows per thread --
__global__ __launch_bounds__(256) void k_dynconv(){
    const int o = blockIdx.x, b = blockIdx.y;
    const int tid = threadIdx.x;
    const int w = tid>>5, lane = tid&31;
    __shared__ float sm[34][35];
    __shared__ float kwsh[9];
    __shared__ float r4[4][8];
    if (tid < 9) kwsh[tid] = g_kw[b*9 + tid];
    if (b == 0 && tid < 16){
        int bb = tid & 7;
        if (tid < 8) g_Sbo [bb*C + o] = 0.f;
        else         g_SSbo[bb*C + o] = 0.f;
    }
    if (tid < 132){
        if (tid < 34)       sm[0][tid] = 0.f;
        else if (tid < 68)  sm[33][tid-34] = 0.f;
        else if (tid < 100) sm[tid-68+1][0] = 0.f;
        else                sm[tid-100+1][33] = 0.f;
    }
    const float sc = g_scale1[o], sh = g_shift1[o];
    const float* plane = &g_A[((size_t)(b*C + o))<<10];
    {
        int r = tid>>3, c4 = (tid&7)<<2;
        float4 v = *reinterpret_cast<const float4*>(&plane[(r<<5)+c4]);
        sm[r+1][c4+1] = v.x*sc+sh;
        sm[r+1][c4+2] = v.y*sc+sh;
        sm[r+1][c4+3] = v.z*sc+sh;
        sm[r+1][c4+4] = v.w*sc+sh;
    }
    __syncthreads();
    const int c = lane, rb = w<<2;
    float v[6][3];
    #pragma unroll
    for (int k=0;k<6;k++){
        #pragma unroll
        for (int j=0;j<3;j++) v[k][j] = sm[rb+k][c+j];
    }
    float lsum=0.f, lss=0.f, lmx=-3.4e38f, lmn=3.4e38f;
    float* dst = &g_B2[(((size_t)(b*C + o))<<10)];
    #pragma unroll
    for (int rr=0;rr<4;rr++){
        float a = 0.f;
        #pragma unroll
        for (int i=0;i<3;i++){
            #pragma unroll
            for (int j=0;j<3;j++) a += kwsh[i*3+j]*v[rr+i][j];
        }
        float g = gelu_f(a);
        dst[((rb+rr)<<5) + c] = g;
        lsum += g; lss += g*g;
        lmx = fmaxf(lmx, g); lmn = fminf(lmn, g);
    }
    #pragma unroll
    for (int off=16;off;off>>=1){
        lsum += __shfl_down_sync(0xffffffffu, lsum, off);
        lss  += __shfl_down_sync(0xffffffffu, lss,  off);
        lmx = fmaxf(lmx, __shfl_down_sync(0xffffffffu, lmx, off));
        lmn = fminf(lmn, __shfl_down_sync(0xffffffffu, lmn, off));
    }
    if (lane==0){ r4[0][w]=lsum; r4[1][w]=lss; r4[2][w]=lmx; r4[3][w]=lmn; }
    __syncthreads();
    if (tid==0){
        float S=0,SS=0,MX=-3.4e38f,MN=3.4e38f;
        for (int i=0;i<8;i++){ S+=r4[0][i]; SS+=r4[1][i]; MX=fmaxf(MX,r4[2][i]); MN=fminf(MN,r4[3][i]); }
        g_S2[b*C+o]=S; g_SS2[b*C+o]=SS; g_Mx2[b*C+o]=MX; g_Mn2[b*C+o]=MN;
    }
}

// ---------------- BN2-finalize + channel attention (Cbd folded into gemm2) ---
__global__ __launch_bounds__(512) void k_cattcbd(const float* __restrict__ g2,
                                                 const float* __restrict__ be2,
                                                 const float* __restrict__ ca_w1,
                                                 const float* __restrict__ ca_w2){
    int b = blockIdx.x, tid = threadIdx.x;
    int w = tid>>5, lane = tid&31;
    __shared__ float sav[C], smv[C], s2c[C], s2h[C], hsum[64];
    for (int i=tid;i<C;i+=512){
        float S=0.f, SS=0.f;
        #pragma unroll
        for (int bb=0;bb<B;bb++){ S += g_S2[bb*C+i]; SS += g_SS2[bb*C+i]; }
        float m = S*(1.f/8192.f), v = SS*(1.f/8192.f) - m*m;
        float rs = rsqrtf(v + 1e-5f);
        float sc = rs*g2[i], sh = be2[i] - m*sc;
        s2c[i]=sc; s2h[i]=sh;
        sav[i] = g_S2[b*C+i]*(1.f/1024.f)*sc + sh;
        float pre = (sc >= 0.f) ? g_Mx2[b*C+i] : g_Mn2[b*C+i];
        smv[i] = pre*sc + sh;
    }
    __syncthreads();
    #pragma unroll
    for (int r=0;r<4;r++){
        int o = (w<<2) + r;
        const float* row = &ca_w1[(size_t)o*C];
        float aa=0.f, am=0.f;
        #pragma unroll 8
        for (int c=lane;c<C;c+=32){ float rv=row[c]; aa += rv*sav[c]; am += rv*smv[c]; }
        #pragma unroll
        for (int off=16;off;off>>=1){
            aa += __shfl_down_sync(0xffffffffu, aa, off);
            am += __shfl_down_sync(0xffffffffu, am, off);
        }
        if (lane==0) hsum[o] = fmaxf(aa,0.f) + fmaxf(am,0.f);
    }
    __syncthreads();
    #pragma unroll
    for (int r=0;r<2;r++){
        int c = tid + (r<<9);
        const float4* w2r = reinterpret_cast<const float4*>(&ca_w2[(size_t)c*64]);
        float a = 0.f;
        #pragma unroll
        for (int j=0;j<16;j++){
            float4 q = w2r[j];
            const float* hh = &hsum[j*4];
            a += q.x*hh[0] + q.y*hh[1] + q.z*hh[2] + q.w*hh[3];
        }
        float s = 1.f/(1.f + expf(-a));
        g_Acoef[b*C+c] = s*s2c[c];
        g_Bcoef[b*C+c] = s*s2h[c];
    }
}

// ---------------- spatial mean/max partials ----------------
__global__ __launch_bounds__(1024) void k_spstats(){
    int b = blockIdx.z, csp = blockIdx.y, sblk = blockIdx.x;
    int tid = threadIdx.x;
    int sl = tid & 63, cg = tid >> 6;
    int s4 = sblk*64 + sl;
    const float4* base4 = reinterpret_cast<const float4*>(&g_B2[((size_t)b)<<20]);
    const float* Ac = &g_Acoef[b*C];
    const float* Bc = &g_Bcoef[b*C];
    float4 sum = make_float4(0,0,0,0);
    float4 mx  = make_float4(-3.4e38f,-3.4e38f,-3.4e38f,-3.4e38f);
    int c0 = csp*256 + cg*16;
    #pragma unroll 4
    for (int c=c0;c<c0+16;c++){
        float4 v = base4[(c<<8)+s4];
        float a = Ac[c], bb = Bc[c];
        v.x = a*v.x+bb; v.y = a*v.y+bb; v.z = a*v.z+bb; v.w = a*v.w+bb;
        sum.x += v.x; sum.y += v.y; sum.z += v.z; sum.w += v.w;
        mx.x = fmaxf(mx.x,v.x); mx.y = fmaxf(mx.y,v.y);
        mx.z = fmaxf(mx.z,v.z); mx.w = fmaxf(mx.w,v.w);
    }
    __shared__ float4 rs[16][64];
    __shared__ float4 rm[16][64];
    rs[cg][sl] = sum; rm[cg][sl] = mx;
    __syncthreads();
    if (tid < 64){
        float4 S = rs[0][tid], M = rm[0][tid];
        #pragma unroll
        for (int g=1; g<16; g++){
            float4 s2 = rs[g][tid], m2 = rm[g][tid];
            S.x+=s2.x; S.y+=s2.y; S.z+=s2.z; S.w+=s2.w;
            M.x=fmaxf(M.x,m2.x); M.y=fmaxf(M.y,m2.y); M.z=fmaxf(M.z,m2.z); M.w=fmaxf(M.w,m2.w);
        }
        int s4o = sblk*64 + tid;
        reinterpret_cast<float4*>(&g_sppsum[(csp*B + b)*HW])[s4o] = S;
        reinterpret_cast<float4*>(&g_sppmax[(csp*B + b)*HW])[s4o] = M;
    }
}

// ---------------- 7x7 spatial conv + sigmoid (+ zero Sd3 before gemm2) -------
__global__ void k_spconv(const float* __restrict__ sw, const float* __restrict__ sb){
    int b = blockIdx.x, tid = threadIdx.x;
    __shared__ float sa[1024], sx[1024];
    __shared__ float kw[98];
    if (b == 0){ g_Sd3[tid] = 0.f; g_SSd3[tid] = 0.f; }
    for (int i=tid;i<1024;i+=256){
        float s0 = g_sppsum[(0*B+b)*HW+i] + g_sppsum[(1*B+b)*HW+i]
                 + g_sppsum[(2*B+b)*HW+i] + g_sppsum[(3*B+b)*HW+i];
        float m0 = fmaxf(fmaxf(g_sppmax[(0*B+b)*HW+i], g_sppmax[(1*B+b)*HW+i]),
                         fmaxf(g_sppmax[(2*B+b)*HW+i], g_sppmax[(3*B+b)*HW+i]));
        sa[i] = s0*(1.f/1024.f);
        sx[i] = m0;
    }
    if (tid < 98) kw[tid] = sw[tid];
    __syncthreads();
    float bias = sb[0];
    for (int p=tid;p<1024;p+=256){
        int ph = p>>5, pw_ = p&31;
        float acc = bias;
        #pragma unroll
        for (int i=0;i<7;i++){
            int hh = ph + i - 3;
            if ((unsigned)hh >= 32u) continue;
            #pragma unroll
            for (int j=0;j<7;j++){
                int ww = pw_ + j - 3;
                if ((unsigned)ww >= 32u) continue;
                acc += kw[i*7+j]*sa[(hh<<5)+ww] + kw[49+i*7+j]*sx[(hh<<5)+ww];
            }
        }
        g_spatt[b*HW+p] = 1.f/(1.f + expf(-acc));
    }
}

// ======= GEMM2: tf32 mma.sync + ldmatrix A, CTA 64x128; X = Acoef*B2 + Bcoef =
__global__ __launch_bounds__(256,3) void k_gemm2(const float* __restrict__ pw,
                                                 const float* __restrict__ pb){
    const int b = blockIdx.z;
    const int dBase = blockIdx.y<<6, sBase = blockIdx.x<<7;
    const int tid = threadIdx.x, lane = tid&31, wid = tid>>5;
    const int g = lane>>2, t = lane&3;
    const int d0 = (wid&1)<<5, s0 = (wid>>1)<<5;
    __shared__ __align__(16) unsigned Ws[2][64][20];
    __shared__ __align__(16) unsigned Xs[2][16][136];

    float acc[2][4][4];
    #pragma unroll
    for (int mi=0;mi<2;mi++){
        #pragma unroll
        for (int ni=0;ni<4;ni++){
            #pragma unroll
            for (int r=0;r<4;r++) acc[mi][ni][r]=0.f;
        }
    }

    const float* Ac  = &g_Acoef[b*C];
    const float* Bc  = &g_Bcoef[b*C];
    const float* src = &g_B2[((size_t)b)<<20];
    const int rw = tid>>2, kqw = (tid&3)*4;   // W: 64 rows x 16 k
    const int kx = tid>>4, sqx = (tid&15)*8;  // X: 16 k rows x 128 s
    const float* wp = pw + (size_t)(dBase+rw)*C + kqw;
    const float* xp = src + ((size_t)kx<<10) + sBase + sqx;

    float4 wv  = *reinterpret_cast<const float4*>(wp);
    float4 xv0 = *reinterpret_cast<const float4*>(xp);
    float4 xv1 = *reinterpret_cast<const float4*>(xp+4);
    float  av  = Ac[kx];
    float  bv  = Bc[kx];

    const int a_row = d0 + ((lane>>3)&1)*8 + (lane&7);
    const int a_col = (lane>>4)<<2;
    const uint32_t aBase = s32(&Ws[0][a_row][a_col]);
    const uint32_t BUFO = 64*20*4;
    const uint32_t T16  = 16*20*4;

    const int NC = C/16;  // 64
    for (int ck=0; ck<NC; ck++){
        const int bf = ck&1;
        {
            uint4 q;
            q.x=tf32f(wv.x); q.y=tf32f(wv.y); q.z=tf32f(wv.z); q.w=tf32f(wv.w);
            *reinterpret_cast<uint4*>(&Ws[bf][rw][kqw]) = q;
            uint4 p0, p1;
            p0.x=tf32f(xv0.x*av+bv); p0.y=tf32f(xv0.y*av+bv);
            p0.z=tf32f(xv0.z*av+bv); p0.w=tf32f(xv0.w*av+bv);
            p1.x=tf32f(xv1.x*av+bv); p1.y=tf32f(xv1.y*av+bv);
            p1.z=tf32f(xv1.z*av+bv); p1.w=tf32f(xv1.w*av+bv);
            *reinterpret_cast<uint4*>(&Xs[bf][kx][sqx])   = p0;
            *reinterpret_cast<uint4*>(&Xs[bf][kx][sqx+4]) = p1;
        }
        __syncthreads();
        if (ck+1 < NC){
            int koff = (ck+1)*16;
            wv  = *reinterpret_cast<const float4*>(wp + koff);
            xv0 = *reinterpret_cast<const float4*>(xp + ((size_t)koff<<10));
            xv1 = *reinterpret_cast<const float4*>(xp + ((size_t)koff<<10) + 4);
            av  = Ac[koff + kx];
            bv  = Bc[koff + kx];
        }
        const uint32_t bo = bf ? BUFO : 0u;
        #pragma unroll
        for (int ks=0; ks<2; ks++){
            const int kb = ks*8;
            unsigned af[2][4];
            ldsm4(af[0][0],af[0][1],af[0][2],af[0][3], aBase + bo + ks*32);
            ldsm4(af[1][0],af[1][1],af[1][2],af[1][3], aBase + bo + ks*32 + T16);
            unsigned bfr[4][2];
            #pragma unroll
            for (int ni=0;ni<4;ni++){
                bfr[ni][0] = Xs[bf][kb+t  ][s0+(ni<<3)+g];
                bfr[ni][1] = Xs[bf][kb+t+4][s0+(ni<<3)+g];
            }
            #pragma unroll
            for (int mi=0;mi<2;mi++){
                #pragma unroll
                for (int ni=0;ni<4;ni++) mma8(acc[mi][ni], af[mi], bfr[ni]);
            }
        }
    }
    // epilogue: spatial att + pb, write Z, BN3 stats (Cbd already inside acc)
    #pragma unroll
    for (int mi=0;mi<2;mi++){
        #pragma unroll
        for (int h=0;h<2;h++){
            int d = dBase + d0 + (mi<<4) + (h<<3) + g;
            float pbv = pb[d];
            float s_=0.f, ss_=0.f;
            float* dst = &g_Z[(((size_t)b*D + d)<<10) + sBase + s0];
            #pragma unroll
            for (int ni=0;ni<4;ni++){
                int sof = (ni<<3) + 2*t;
                float2 sp = *reinterpret_cast<const float2*>(&g_spatt[b*HW + sBase + s0 + sof]);
                float z0 = sp.x*acc[mi][ni][2*h  ] + pbv;
                float z1 = sp.y*acc[mi][ni][2*h+1] + pbv;
                *reinterpret_cast<float2*>(dst + sof) = make_float2(z0,z1);
                s_ += z0+z1; ss_ += z0*z0 + z1*z1;
            }
            s_  += __shfl_xor_sync(0xffffffffu, s_, 1);
            s_  += __shfl_xor_sync(0xffffffffu, s_, 2);
            ss_ += __shfl_xor_sync(0xffffffffu, ss_, 1);
            ss_ += __shfl_xor_sync(0xffffffffu, ss_, 2);
            if (t==0){
                atomicAdd(&g_Sd3 [d], s_);
                atomicAdd(&g_SSd3[d], ss_);
            }
        }
    }
}

// ---------------- transpose + BN3 (inline finalize) + residual ----------------
__global__ void k_out(const float* __restrict__ x, float* __restrict__ out,
                      const float* __restrict__ g3, const float* __restrict__ be3){
    const int b = blockIdx.z;
    const int dB = blockIdx.y<<5, sB = blockIdx.x<<5;
    const int tx = threadIdx.x, ty = threadIdx.y;
    __shared__ float sm[32][33];
    #pragma unroll
    for (int r=0;r<4;r++){
        int dd = ty + (r<<3);
        sm[dd][tx] = g_Z[(((size_t)b*D + dB + dd)<<10) + sB + tx];
    }
    int d = dB + tx;
    float m = g_Sd3[d]*(1.f/8192.f);
    float v = g_SSd3[d]*(1.f/8192.f) - m*m;
    float sc = rsqrtf(v + 1e-5f)*g3[d];
    float sh = be3[d] - m*sc;
    __syncthreads();
    #pragma unroll
    for (int r=0;r<4;r++){
        int ss = ty + (r<<3);
        size_t oi = ((size_t)(b*HW) + sB + ss)*D + d;
        out[oi] = x[oi] + sm[tx][ss]*sc + sh;
    }
}

extern "C" void kernel_launch(void* const* d_in, const int* in_sizes, int n_in,
                              void* d_out, int out_size){
    const float* x     = (const float*)d_in[0];
    const float* w1    = (const float*)d_in[1];
    const float* b1    = (const float*)d_in[2];
    const float* g1    = (const float*)d_in[3];
    const float* be1   = (const float*)d_in[4];
    const float* aw1   = (const float*)d_in[5];
    const float* ab1   = (const float*)d_in[6];
    const float* aw2   = (const float*)d_in[7];
    const float* ab2   = (const float*)d_in[8];
    const float* g2    = (const float*)d_in[9];
    const float* be2   = (const float*)d_in[10];
    const float* ca_w1 = (const float*)d_in[11];
    const float* ca_w2 = (const float*)d_in[12];
    const float* pw    = (const float*)d_in[13];
    const float* pb    = (const float*)d_in[14];
    const float* g3    = (const float*)d_in[15];
    const float* be3   = (const float*)d_in[16];
    const float* sw    = (const float*)d_in[17];
    const float* sb    = (const float*)d_in[18];
    float* out = (float*)d_out;

    k_gemm1   <<<dim3(8,8,B), 256>>>(x, w1, b1);
    k_dynw    <<<B, 1024>>>(g1, be1, aw1, ab1, aw2, ab2);
    k_dynconv <<<dim3(C,B), 256>>>();
    k_cattcbd <<<B, 512>>>(g2, be2, ca_w1, ca_w2);
    k_spstats <<<dim3(4,4,B), 1024>>>();
    k_spconv  <<<B, 256>>>(sw, sb);
    k_gemm2   <<<dim3(8,4,B), 256>>>(pw, pb);
    k_out     <<<dim3(32,8,B), dim3(32,8)>>>(x, out, g3, be3);
}

// round 17
// speedup vs baseline: 1.2504x; 1.0404x over previous
#include <cuda_runtime.h>
#include <math.h>
#include <stdint.h>

#define B 8
#define D 256
#define C 1024
#define HW 1024

typedef unsigned long long u64;

// ---------------- scratch (zero-initialized at module load; accumulators are
// re-zeroed by kernel tails each iteration so graph replays stay deterministic)
__device__ float g_A [B*C*HW];
__device__ float g_B2[B*C*HW];
__device__ float g_Z [B*D*HW];
__device__ float g_Sbo[B*C], g_SSbo[B*C];
__device__ float g_scale1[C], g_shift1[C];
__device__ float g_kw[B*9];
__device__ float g_S2[B*C], g_SS2[B*C], g_Mx2[B*C], g_Mn2[B*C];
__device__ float g_s2c[C], g_s2h[C];
__device__ float g_avg2[B*C], g_max2[B*C];
__device__ float g_hsum[B*64];
__device__ float g_Acoef[B*C], g_Bcoef[B*C];
__device__ float g_sppsum[4*B*HW], g_sppmax[4*B*HW];
__device__ float g_spatt[B*HW];
__device__ float g_Sd3[D], g_SSd3[D];

__device__ __forceinline__ float gelu_f(float x){
    return 0.5f*x*(1.0f + erff(x*0.70710678118654752440f));
}
__device__ __forceinline__ unsigned tf32f(float v){
    unsigned r; asm("cvt.rna.tf32.f32 %0, %1;" : "=r"(r) : "f"(v)); return r;
}
__device__ __forceinline__ void mma8(float* c, const unsigned* a, const unsigned* b){
    asm volatile("mma.sync.aligned.m16n8k8.row.col.f32.tf32.tf32.f32 "
        "{%0,%1,%2,%3}, {%4,%5,%6,%7}, {%8,%9}, {%0,%1,%2,%3};"
        : "+f"(c[0]), "+f"(c[1]), "+f"(c[2]), "+f"(c[3])
        : "r"(a[0]), "r"(a[1]), "r"(a[2]), "r"(a[3]),
          "r"(b[0]), "r"(b[1]));
}
__device__ __forceinline__ uint32_t s32(const void* p){
    uint32_t a;
    asm("{ .reg .u64 t; cvta.to.shared.u64 t, %1; cvt.u32.u64 %0, t; }" : "=r"(a) : "l"(p));
    return a;
}
__device__ __forceinline__ void ldsm4(unsigned &r0, unsigned &r1, unsigned &r2, unsigned &r3, uint32_t a){
    asm volatile("ldmatrix.sync.aligned.m8n8.x4.shared.b16 {%0,%1,%2,%3}, [%4];"
        : "=r"(r0), "=r"(r1), "=r"(r2), "=r"(r3) : "r"(a));
}

// ================= GEMM1: tf32 mma.sync + ldmatrix, CTA 128x128, warps 4Mx2N =
__global__ __launch_bounds__(256,2) void k_gemm1(const float* __restrict__ x,
                                                 const float* __restrict__ w1,
                                                 const float* __restrict__ b1){
    const int b = blockIdx.z;
    const int oBase = blockIdx.y<<7, sBase = blockIdx.x<<7;
    const int tid = threadIdx.x, lane = tid&31, wid = tid>>5;
    const int g = lane>>2, t = lane&3;
    const int o0 = (wid&3)<<5, s0 = (wid>>2)<<6;
    __shared__ __align__(16) unsigned Ws[2][128][20];
    __shared__ __align__(16) unsigned Xs[2][128][20];

    float acc[2][8][4];
    #pragma unroll
    for (int mi=0;mi<2;mi++){
        #pragma unroll
        for (int ni=0;ni<8;ni++){
            #pragma unroll
            for (int r=0;r<4;r++) acc[mi][ni][r]=0.f;
        }
    }

    const int rl = tid>>1, kq = (tid&1)*8;
    const float* wp = w1 + (size_t)(oBase+rl)*D + kq;
    const float* xp = x + (size_t)(b*HW + sBase + rl)*D + kq;

    float4 wv0 = *reinterpret_cast<const float4*>(wp);
    float4 wv1 = *reinterpret_cast<const float4*>(wp+4);
    float4 xv0 = *reinterpret_cast<const float4*>(xp);
    float4 xv1 = *reinterpret_cast<const float4*>(xp+4);

    const int a_row = o0 + ((lane>>3)&1)*8 + (lane&7);
    const int a_col = (lane>>4)<<2;
    const int b_row = s0 + ((lane>>4)&1)*8 + (lane&7);
    const int b_col = ((lane>>3)&1)*4;
    const uint32_t aBase = s32(&Ws[0][a_row][a_col]);
    const uint32_t bBase = s32(&Xs[0][b_row][b_col]);
    const uint32_t BUFO = 128*20*4;
    const uint32_t T16  = 16*20*4;

    const int NC = D/16;  // 16
    for (int ck=0; ck<NC; ck++){
        const int bf = ck&1;
        {
            uint4 q0, q1;
            q0.x=tf32f(wv0.x); q0.y=tf32f(wv0.y); q0.z=tf32f(wv0.z); q0.w=tf32f(wv0.w);
            q1.x=tf32f(wv1.x); q1.y=tf32f(wv1.y); q1.z=tf32f(wv1.z); q1.w=tf32f(wv1.w);
            *reinterpret_cast<uint4*>(&Ws[bf][rl][kq])   = q0;
            *reinterpret_cast<uint4*>(&Ws[bf][rl][kq+4]) = q1;
            q0.x=tf32f(xv0.x); q0.y=tf32f(xv0.y); q0.z=tf32f(xv0.z); q0.w=tf32f(xv0.w);
            q1.x=tf32f(xv1.x); q1.y=tf32f(xv1.y); q1.z=tf32f(xv1.z); q1.w=tf32f(xv1.w);
            *reinterpret_cast<uint4*>(&Xs[bf][rl][kq])   = q0;
            *reinterpret_cast<uint4*>(&Xs[bf][rl][kq+4]) = q1;
        }
        __syncthreads();
        if (ck+1 < NC){
            int koff = (ck+1)*16;
            wv0 = *reinterpret_cast<const float4*>(wp + koff);
            wv1 = *reinterpret_cast<const float4*>(wp + koff + 4);
            xv0 = *reinterpret_cast<const float4*>(xp + koff);
            xv1 = *reinterpret_cast<const float4*>(xp + koff + 4);
        }
        const uint32_t bo = bf ? BUFO : 0u;
        #pragma unroll
        for (int ks=0; ks<2; ks++){
            const uint32_t ko = bo + ks*32;
            unsigned af[2][4];
            ldsm4(af[0][0],af[0][1],af[0][2],af[0][3], aBase + ko);
            ldsm4(af[1][0],af[1][1],af[1][2],af[1][3], aBase + ko + T16);
            unsigned bq[4][4];
            #pragma unroll
            for (int np=0;np<4;np++)
                ldsm4(bq[np][0],bq[np][1],bq[np][2],bq[np][3], bBase + ko + np*T16);
            #pragma unroll
            for (int mi=0;mi<2;mi++){
                #pragma unroll
                for (int ni=0;ni<8;ni++) mma8(acc[mi][ni], af[mi], &bq[ni>>1][(ni&1)*2]);
            }
        }
    }
    #pragma unroll
    for (int mi=0;mi<2;mi++){
        #pragma unroll
        for (int h=0;h<2;h++){
            int o = oBase + o0 + (mi<<4) + (h<<3) + g;
            float bias = b1[o];
            float s_=0.f, ss_=0.f;
            float* dst = &g_A[(((size_t)b*C + o)<<10) + sBase + s0];
            #pragma unroll
            for (int ni=0;ni<8;ni++){
                float v0 = gelu_f(acc[mi][ni][2*h  ] + bias);
                float v1 = gelu_f(acc[mi][ni][2*h+1] + bias);
                *reinterpret_cast<float2*>(dst + (ni<<3) + 2*t) = make_float2(v0,v1);
                s_ += v0+v1; ss_ += v0*v0 + v1*v1;
            }
            s_  += __shfl_xor_sync(0xffffffffu, s_, 1);
            s_  += __shfl_xor_sync(0xffffffffu, s_, 2);
            ss_ += __shfl_xor_sync(0xffffffffu, ss_, 1);
            ss_ += __shfl_xor_sync(0xffffffffu, ss_, 2);
            if (t==0){
                atomicAdd(&g_Sbo [b*C+o], s_);
                atomicAdd(&g_SSbo[b*C+o], ss_);
            }
        }
    }
}

// ------- dynw: BN1 finalize + GAP (in-smem) + FC1 + FC2 + softmax, one kernel
__global__ __launch_bounds__(1024) void k_dynw(const float* __restrict__ g1,
                                               const float* __restrict__ be1,
                                               const float* __restrict__ aw1,
                                               const float* __restrict__ ab1,
                                               const float* __restrict__ aw2,
                                               const float* __restrict__ ab2){
    int b = blockIdx.x, tid = threadIdx.x;
    int w = tid>>5, lane = tid&31;
    __shared__ float gaps[C];
    __shared__ float h1s[128];
    __shared__ float logits[9];
    {
        int o = tid;
        float S=0.f, SS=0.f;
        #pragma unroll
        for (int bb=0;bb<B;bb++){ S += g_Sbo[bb*C+o]; SS += g_SSbo[bb*C+o]; }
        float m = S*(1.f/8192.f), v = SS*(1.f/8192.f) - m*m;
        float rs = rsqrtf(v + 1e-5f);
        float sc = rs*g1[o], sh = be1[o] - m*sc;
        g_scale1[o]=sc; g_shift1[o]=sh;
        gaps[o] = g_Sbo[b*C+o]*(1.f/1024.f)*sc + sh;
    }
    __syncthreads();
    float4 gv[8];
    const float4* gp = reinterpret_cast<const float4*>(gaps);
    #pragma unroll
    for (int i=0;i<8;i++) gv[i] = gp[lane + 32*i];
    #pragma unroll
    for (int r=0;r<4;r++){
        int o = (w<<2) + r;
        const float4* row = reinterpret_cast<const float4*>(&aw1[(size_t)o*C]);
        float a = 0.f;
        #pragma unroll
        for (int i=0;i<8;i++){
            float4 wv = row[lane + 32*i];
            a += wv.x*gv[i].x + wv.y*gv[i].y + wv.z*gv[i].z + wv.w*gv[i].w;
        }
        #pragma unroll
        for (int off=16;off;off>>=1) a += __shfl_down_sync(0xffffffffu, a, off);
        if (lane==0) h1s[o] = fmaxf(a + ab1[o], 0.f);
    }
    __syncthreads();
    if (w < 9){
        float4 q = reinterpret_cast<const float4*>(&aw2[w*128])[lane];
        const float* hh = &h1s[lane*4];
        float l = q.x*hh[0] + q.y*hh[1] + q.z*hh[2] + q.w*hh[3];
        #pragma unroll
        for (int off=16;off;off>>=1) l += __shfl_down_sync(0xffffffffu, l, off);
        if (lane==0) logits[w] = l + ab2[w];
    }
    __syncthreads();
    if (tid==0){
        float mx = logits[0];
        for (int jj=1;jj<9;jj++) mx = fmaxf(mx, logits[jj]);
        float e[9], Zs=0.f;
        for (int jj=0;jj<9;jj++){ e[jj]=expf(logits[jj]-mx); Zs+=e[jj]; }
        float inv = 1.f/Zs;
        for (int jj=0;jj<9;jj++) g_kw[b*9+jj] = e[jj]*inv;
    }
}

// ---- dynamic depthwise conv + gelu + BN2 stats: 4 adjacent rows per thread --
__global__ __launch_bounds__(256) void k_dynconv(){
    const int o = blockIdx.x, b = blockIdx.y;
    const int tid = threadIdx.x;
    const int w = tid>>5, lane = tid&31;
    __shared__ float sm[34][35];
    __shared__ float kwsh[9];
    __shared__ float r4[4][8];
    if (tid < 9) kwsh[tid] = g_kw[b*9 + tid];
    if (b == 0 && tid < 16){
        int bb = tid & 7;
        if (tid < 8) g_Sbo [bb*C + o] = 0.f;
        else         g_SSbo[bb*C + o] = 0.f;
    }
    if (tid < 132){
        if (tid < 34)       sm[0][tid] = 0.f;
        else if (tid < 68)  sm[33][tid-34] = 0.f;
        else if (tid < 100) sm[tid-68+1][0] = 0.f;
        else                sm[tid-100+1][33] = 0.f;
    }
    const float sc = g_scale1[o], sh = g_shift1[o];
    const float* plane = &g_A[((size_t)(b*C + o))<<10];
    {
        int r = tid>>3, c4 = (tid&7)<<2;
        float4 v = *reinterpret_cast<const float4*>(&plane[(r<<5)+c4]);
        sm[r+1][c4+1] = v.x*sc+sh;
        sm[r+1][c4+2] = v.y*sc+sh;
        sm[r+1][c4+3] = v.z*sc+sh;
        sm[r+1][c4+4] = v.w*sc+sh;
    }
    __syncthreads();
    const int c = lane, rb = w<<2;
    float v[6][3];
    #pragma unroll
    for (int k=0;k<6;k++){
        #pragma unroll
        for (int j=0;j<3;j++) v[k][j] = sm[rb+k][c+j];
    }
    float lsum=0.f, lss=0.f, lmx=-3.4e38f, lmn=3.4e38f;
    float* dst = &g_B2[(((size_t)(b*C + o))<<10)];
    #pragma unroll
    for (int rr=0;rr<4;rr++){
        float a = 0.f;
        #pragma unroll
        for (int i=0;i<3;i++){
            #pragma unroll
            for (int j=0;j<3;j++) a += kwsh[i*3+j]*v[rr+i][j];
        }
        float g = gelu_f(a);
        dst[((rb+rr)<<5) + c] = g;
        lsum += g; lss += g*g;
        lmx = fmaxf(lmx, g); lmn = fminf(lmn, g);
    }
    #pragma unroll
    for (int off=16;off;off>>=1){
        lsum += __shfl_down_sync(0xffffffffu, lsum, off);
        lss  += __shfl_down_sync(0xffffffffu, lss,  off);
        lmx = fmaxf(lmx, __shfl_down_sync(0xffffffffu, lmx, off));
        lmn = fminf(lmn, __shfl_down_sync(0xffffffffu, lmn, off));
    }
    if (lane==0){ r4[0][w]=lsum; r4[1][w]=lss; r4[2][w]=lmx; r4[3][w]=lmn; }
    __syncthreads();
    if (tid==0){
        float S=0,SS=0,MX=-3.4e38f,MN=3.4e38f;
        for (int i=0;i<8;i++){ S+=r4[0][i]; SS+=r4[1][i]; MX=fmaxf(MX,r4[2][i]); MN=fminf(MN,r4[3][i]); }
        g_S2[b*C+o]=S; g_SS2[b*C+o]=SS; g_Mx2[b*C+o]=MX; g_Mn2[b*C+o]=MN;
    }
}

// ---------------- BN2 finalize: per-channel scale/shift + per-(b,c) avg/max --
__global__ __launch_bounds__(256) void k_bn2fin(const float* __restrict__ g2,
                                                const float* __restrict__ be2){
    int b = blockIdx.y;
    int c = blockIdx.x*256 + threadIdx.x;
    float S=0.f, SS=0.f;
    #pragma unroll
    for (int bb=0;bb<B;bb++){ S += g_S2[bb*C+c]; SS += g_SS2[bb*C+c]; }
    float m = S*(1.f/8192.f), v = SS*(1.f/8192.f) - m*m;
    float rs = rsqrtf(v + 1e-5f);
    float sc = rs*g2[c], sh = be2[c] - m*sc;
    if (b == 0){ g_s2c[c]=sc; g_s2h[c]=sh; }
    g_avg2[b*C+c] = g_S2[b*C+c]*(1.f/1024.f)*sc + sh;
    float pre = (sc >= 0.f) ? g_Mx2[b*C+c] : g_Mn2[b*C+c];
    g_max2[b*C+c] = pre*sc + sh;
}

// ---------------- channel attention squeeze: warp-per-output FC1 ------------
__global__ __launch_bounds__(256) void k_catt1(const float* __restrict__ ca_w1){
    int b = blockIdx.y, og = blockIdx.x;
    int w = threadIdx.x>>5, lane = threadIdx.x&31;
    int o = og*8 + w;
    const float4* row = reinterpret_cast<const float4*>(&ca_w1[(size_t)o*C]);
    const float4* av  = reinterpret_cast<const float4*>(&g_avg2[b*C]);
    const float4* mv  = reinterpret_cast<const float4*>(&g_max2[b*C]);
    float aa=0.f, am=0.f;
    #pragma unroll
    for (int i=0;i<8;i++){
        float4 wv = row[lane + 32*i];
        float4 a = av[lane + 32*i];
        float4 m = mv[lane + 32*i];
        aa += wv.x*a.x + wv.y*a.y + wv.z*a.z + wv.w*a.w;
        am += wv.x*m.x + wv.y*m.y + wv.z*m.z + wv.w*m.w;
    }
    #pragma unroll
    for (int off=16;off;off>>=1){
        aa += __shfl_down_sync(0xffffffffu, aa, off);
        am += __shfl_down_sync(0xffffffffu, am, off);
    }
    if (lane==0) g_hsum[b*64+o] = fmaxf(aa,0.f) + fmaxf(am,0.f);
}

// ---------------- channel attention excite: FC2 + sigmoid -> Acoef/Bcoef ----
__global__ __launch_bounds__(256) void k_catt2(const float* __restrict__ ca_w2){
    int b = blockIdx.y;
    int c = blockIdx.x*256 + threadIdx.x;
    __shared__ float hs[64];
    if (threadIdx.x < 64) hs[threadIdx.x] = g_hsum[b*64+threadIdx.x];
    __syncthreads();
    const float4* w2r = reinterpret_cast<const float4*>(&ca_w2[(size_t)c*64]);
    float a = 0.f;
    #pragma unroll
    for (int j=0;j<16;j++){
        float4 q = w2r[j];
        const float* hh = &hs[j*4];
        a += q.x*hh[0] + q.y*hh[1] + q.z*hh[2] + q.w*hh[3];
    }
    float s = 1.f/(1.f + expf(-a));
    g_Acoef[b*C+c] = s*g_s2c[c];
    g_Bcoef[b*C+c] = s*g_s2h[c];
}

// ---------------- spatial mean/max partials ----------------
__global__ __launch_bounds__(1024) void k_spstats(){
    int b = blockIdx.z, csp = blockIdx.y, sblk = blockIdx.x;
    int tid = threadIdx.x;
    int sl = tid & 63, cg = tid >> 6;
    int s4 = sblk*64 + sl;
    const float4* base4 = reinterpret_cast<const float4*>(&g_B2[((size_t)b)<<20]);
    const float* Ac = &g_Acoef[b*C];
    const float* Bc = &g_Bcoef[b*C];
    float4 sum = make_float4(0,0,0,0);
    float4 mx  = make_float4(-3.4e38f,-3.4e38f,-3.4e38f,-3.4e38f);
    int c0 = csp*256 + cg*16;
    #pragma unroll 4
    for (int c=c0;c<c0+16;c++){
        float4 v = base4[(c<<8)+s4];
        float a = Ac[c], bb = Bc[c];
        v.x = a*v.x+bb; v.y = a*v.y+bb; v.z = a*v.z+bb; v.w = a*v.w+bb;
        sum.x += v.x; sum.y += v.y; sum.z += v.z; sum.w += v.w;
        mx.x = fmaxf(mx.x,v.x); mx.y = fmaxf(mx.y,v.y);
        mx.z = fmaxf(mx.z,v.z); mx.w = fmaxf(mx.w,v.w);
    }
    __shared__ float4 rs[16][64];
    __shared__ float4 rm[16][64];
    rs[cg][sl] = sum; rm[cg][sl] = mx;
    __syncthreads();
    if (tid < 64){
        float4 S = rs[0][tid], M = rm[0][tid];
        #pragma unroll
        for (int g=1; g<16; g++){
            float4 s2 = rs[g][tid], m2 = rm[g][tid];
            S.x+=s2.x; S.y+=s2.y; S.z+=s2.z; S.w+=s2.w;
            M.x=fmaxf(M.x,m2.x); M.y=fmaxf(M.y,m2.y); M.z=fmaxf(M.z,m2.z); M.w=fmaxf(M.w,m2.w);
        }
        int s4o = sblk*64 + tid;
        reinterpret_cast<float4*>(&g_sppsum[(csp*B + b)*HW])[s4o] = S;
        reinterpret_cast<float4*>(&g_sppmax[(csp*B + b)*HW])[s4o] = M;
    }
}

// ---------------- 7x7 spatial conv + sigmoid (+ zero Sd3 before gemm2) -------
__global__ void k_spconv(const float* __restrict__ sw, const float* __restrict__ sb){
    int b = blockIdx.x, tid = threadIdx.x;
    __shared__ float sa[1024], sx[1024];
    __shared__ float kw[98];
    if (b == 0){ g_Sd3[tid] = 0.f; g_SSd3[tid] = 0.f; }
    for (int i=tid;i<1024;i+=256){
        float s0 = g_sppsum[(0*B+b)*HW+i] + g_sppsum[(1*B+b)*HW+i]
                 + g_sppsum[(2*B+b)*HW+i] + g_sppsum[(3*B+b)*HW+i];
        float m0 = fmaxf(fmaxf(g_sppmax[(0*B+b)*HW+i], g_sppmax[(1*B+b)*HW+i]),
                         fmaxf(g_sppmax[(2*B+b)*HW+i], g_sppmax[(3*B+b)*HW+i]));
        sa[i] = s0*(1.f/1024.f);
        sx[i] = m0;
    }
    if (tid < 98) kw[tid] = sw[tid];
    __syncthreads();
    float bias = sb[0];
    for (int p=tid;p<1024;p+=256){
        int ph = p>>5, pw_ = p&31;
        float acc = bias;
        #pragma unroll
        for (int i=0;i<7;i++){
            int hh = ph + i - 3;
            if ((unsigned)hh >= 32u) continue;
            #pragma unroll
            for (int j=0;j<7;j++){
                int ww = pw_ + j - 3;
                if ((unsigned)ww >= 32u) continue;
                acc += kw[i*7+j]*sa[(hh<<5)+ww] + kw[49+i*7+j]*sx[(hh<<5)+ww];
            }
        }
        g_spatt[b*HW+p] = 1.f/(1.f + expf(-acc));
    }
}

// ======= GEMM2: tf32 mma.sync + ldmatrix A, CTA 64x128; X = Acoef*B2 + Bcoef =
__global__ __launch_bounds__(256,3) void k_gemm2(const float* __restrict__ pw,
                                                 const float* __restrict__ pb){
    const int b = blockIdx.z;
    const int dBase = blockIdx.y<<6, sBase = blockIdx.x<<7;
    const int tid = threadIdx.x, lane = tid&31, wid = tid>>5;
    const int g = lane>>2, t = lane&3;
    const int d0 = (wid&1)<<5, s0 = (wid>>1)<<5;
    __shared__ __align__(16) unsigned Ws[2][64][20];
    __shared__ __align__(16) unsigned Xs[2][16][136];

    float acc[2][4][4];
    #pragma unroll
    for (int mi=0;mi<2;mi++){
        #pragma unroll
        for (int ni=0;ni<4;ni++){
            #pragma unroll
            for (int r=0;r<4;r++) acc[mi][ni][r]=0.f;
        }
    }

    const float* Ac  = &g_Acoef[b*C];
    const float* Bc  = &g_Bcoef[b*C];
    const float* src = &g_B2[((size_t)b)<<20];
    const int rw = tid>>2, kqw = (tid&3)*4;   // W: 64 rows x 16 k
    const int kx = tid>>4, sqx = (tid&15)*8;  // X: 16 k rows x 128 s
    const float* wp = pw + (size_t)(dBase+rw)*C + kqw;
    const float* xp = src + ((size_t)kx<<10) + sBase + sqx;

    float4 wv  = *reinterpret_cast<const float4*>(wp);
    float4 xv0 = *reinterpret_cast<const float4*>(xp);
    float4 xv1 = *reinterpret_cast<const float4*>(xp+4);
    float  av  = Ac[kx];
    float  bv  = Bc[kx];

    const int a_row = d0 + ((lane>>3)&1)*8 + (lane&7);
    const int a_col = (lane>>4)<<2;
    const uint32_t aBase = s32(&Ws[0][a_row][a_col]);
    const uint32_t BUFO = 64*20*4;
    const uint32_t T16  = 16*20*4;

    const int NC = C/16;  // 64
    for (int ck=0; ck<NC; ck++){
        const int bf = ck&1;
        {
            uint4 q;
            q.x=tf32f(wv.x); q.y=tf32f(wv.y); q.z=tf32f(wv.z); q.w=tf32f(wv.w);
            *reinterpret_cast<uint4*>(&Ws[bf][rw][kqw]) = q;
            uint4 p0, p1;
            p0.x=tf32f(xv0.x*av+bv); p0.y=tf32f(xv0.y*av+bv);
            p0.z=tf32f(xv0.z*av+bv); p0.w=tf32f(xv0.w*av+bv);
            p1.x=tf32f(xv1.x*av+bv); p1.y=tf32f(xv1.y*av+bv);
            p1.z=tf32f(xv1.z*av+bv); p1.w=tf32f(xv1.w*av+bv);
            *reinterpret_cast<uint4*>(&Xs[bf][kx][sqx])   = p0;
            *reinterpret_cast<uint4*>(&Xs[bf][kx][sqx+4]) = p1;
        }
        __syncthreads();
        if (ck+1 < NC){
            int koff = (ck+1)*16;
            wv  = *reinterpret_cast<const float4*>(wp + koff);
            xv0 = *reinterpret_cast<const float4*>(xp + ((size_t)koff<<10));
            xv1 = *reinterpret_cast<const float4*>(xp + ((size_t)koff<<10) + 4);
            av  = Ac[koff + kx];
            bv  = Bc[koff + kx];
        }
        const uint32_t bo = bf ? BUFO : 0u;
        #pragma unroll
        for (int ks=0; ks<2; ks++){
            const int kb = ks*8;
            unsigned af[2][4];
            ldsm4(af[0][0],af[0][1],af[0][2],af[0][3], aBase + bo + ks*32);
            ldsm4(af[1][0],af[1][1],af[1][2],af[1][3], aBase + bo + ks*32 + T16);
            unsigned bfr[4][2];
            #pragma unroll
            for (int ni=0;ni<4;ni++){
                bfr[ni][0] = Xs[bf][kb+t  ][s0+(ni<<3)+g];
                bfr[ni][1] = Xs[bf][kb+t+4][s0+(ni<<3)+g];
            }
            #pragma unroll
            for (int mi=0;mi<2;mi++){
                #pragma unroll
                for (int ni=0;ni<4;ni++) mma8(acc[mi][ni], af[mi], bfr[ni]);
            }
        }
    }
    // epilogue: spatial att + pb, write Z, BN3 stats (Cbd already inside acc)
    #pragma unroll
    for (int mi=0;mi<2;mi++){
        #pragma unroll
        for (int h=0;h<2;h++){
            int d = dBase + d0 + (mi<<4) + (h<<3) + g;
            float pbv = pb[d];
            float s_=0.f, ss_=0.f;
            float* dst = &g_Z[(((size_t)b*D + d)<<10) + sBase + s0];
            #pragma unroll
            for (int ni=0;ni<4;ni++){
                int sof = (ni<<3) + 2*t;
                float2 sp = *reinterpret_cast<const float2*>(&g_spatt[b*HW + sBase + s0 + sof]);
                float z0 = sp.x*acc[mi][ni][2*h  ] + pbv;
                float z1 = sp.y*acc[mi][ni][2*h+1] + pbv;
                *reinterpret_cast<float2*>(dst + sof) = make_float2(z0,z1);
                s_ += z0+z1; ss_ += z0*z0 + z1*z1;
            }
            s_  += __shfl_xor_sync(0xffffffffu, s_, 1);
            s_  += __shfl_xor_sync(0xffffffffu, s_, 2);
            ss_ += __shfl_xor_sync(0xffffffffu, ss_, 1);
            ss_ += __shfl_xor_sync(0xffffffffu, ss_, 2);
            if (t==0){
                atomicAdd(&g_Sd3 [d], s_);
                atomicAdd(&g_SSd3[d], ss_);
            }
        }
    }
}

// ---------------- transpose + BN3 (inline finalize) + residual ----------------
__global__ void k_out(const float* __restrict__ x, float* __restrict__ out,
                      const float* __restrict__ g3, const float* __restrict__ be3){
    const int b = blockIdx.z;
    const int dB = blockIdx.y<<5, sB = blockIdx.x<<5;
    const int tx = threadIdx.x, ty = threadIdx.y;
    __shared__ float sm[32][33];
    #pragma unroll
    for (int r=0;r<4;r++){
        int dd = ty + (r<<3);
        sm[dd][tx] = g_Z[(((size_t)b*D + dB + dd)<<10) + sB + tx];
    }
    int d = dB + tx;
    float m = g_Sd3[d]*(1.f/8192.f);
    float v = g_SSd3[d]*(1.f/8192.f) - m*m;
    float sc = rsqrtf(v + 1e-5f)*g3[d];
    float sh = be3[d] - m*sc;
    __syncthreads();
    #pragma unroll
    for (int r=0;r<4;r++){
        int ss = ty + (r<<3);
        size_t oi = ((size_t)(b*HW) + sB + ss)*D + d;
        out[oi] = x[oi] + sm[tx][ss]*sc + sh;
    }
}

extern "C" void kernel_launch(void* const* d_in, const int* in_sizes, int n_in,
                              void* d_out, int out_size){
    const float* x     = (const float*)d_in[0];
    const float* w1    = (const float*)d_in[1];
    const float* b1    = (const float*)d_in[2];
    const float* g1    = (const float*)d_in[3];
    const float* be1   = (const float*)d_in[4];
    const float* aw1   = (const float*)d_in[5];
    const float* ab1   = (const float*)d_in[6];
    const float* aw2   = (const float*)d_in[7];
    const float* ab2   = (const float*)d_in[8];
    const float* g2    = (const float*)d_in[9];
    const float* be2   = (const float*)d_in[10];
    const float* ca_w1 = (const float*)d_in[11];
    const float* ca_w2 = (const float*)d_in[12];
    const float* pw    = (const float*)d_in[13];
    const float* pb    = (const float*)d_in[14];
    const float* g3    = (const float*)d_in[15];
    const float* be3   = (const float*)d_in[16];
    const float* sw    = (const float*)d_in[17];
    const float* sb    = (const float*)d_in[18];
    float* out = (float*)d_out;

    k_gemm1   <<<dim3(8,8,B), 256>>>(x, w1, b1);
    k_dynw    <<<B, 1024>>>(g1, be1, aw1, ab1, aw2, ab2);
    k_dynconv <<<dim3(C,B), 256>>>();
    k_bn2fin  <<<dim3(4,B), 256>>>(g2, be2);
    k_catt1   <<<dim3(8,B), 256>>>(ca_w1);
    k_catt2   <<<dim3(4,B), 256>>>(ca_w2);
    k_spstats <<<dim3(4,4,B), 1024>>>();
    k_spconv  <<<B, 256>>>(sw, sb);
    k_gemm2   <<<dim3(8,4,B), 256>>>(pw, pb);
    k_out     <<<dim3(32,8,B), dim3(32,8)>>>(x, out, g3, be3);
}